// round 12
// baseline (speedup 1.0000x reference)
#include <cuda_runtime.h>
#include <cuda_fp16.h>
#include <math.h>
#include <stdint.h>

// ---------------- problem constants ----------------
#define TTOK   2048
#define BATCH  2
#define SEQ    1024
#define DIM    1024
#define HEADS  8
#define BH     16
#define QK_HD  128
#define V_HD   128
#define NOPE   64
#define ROPE   64
#define KV_LORA 256
#define KVA_N  320
#define KVB_N  1536
#define N_EXP  32
#define N_GROUPS 8
#define TOPK   4
#define TOPK_G 4
#define INTER  512
#define NSLOT  8192
#define EPS    1e-6f
#define ATTN_SCALE 0.08838834764831843f

typedef __half f16;

// ---------------- scratch ----------------
__device__ float g_kvF [TTOK * KVA_N];
__device__ float g_x2  [TTOK * DIM];
__device__ float g_xf  [TTOK * DIM];
__device__ float g_ybuf[NSLOT * DIM];
__device__ float g_zb  [TTOK * DIM];

__device__ f16 g_x1h [TTOK * DIM];
__device__ f16 g_qh  [TTOK * DIM];
__device__ f16 g_cnh [TTOK * KV_LORA];
__device__ f16 g_kvph[TTOK * KVB_N];
__device__ f16 g_khh [(size_t)BH * SEQ * QK_HD];
__device__ f16 g_Ph  [(size_t)BH * SEQ * SEQ];   // scores (f16) -> softmaxed in place
__device__ f16 g_attnh[TTOK * DIM];
__device__ f16 g_xfh [TTOK * DIM];
__device__ f16 g_hbufh[NSLOT * INTER];
__device__ f16 g_hsh [TTOK * INTER];

// f16 copies of routed-expert weights (filled each call on side stream)
__device__ f16 g_ew1h[(size_t)N_EXP * DIM * INTER];
__device__ f16 g_ew3h[(size_t)N_EXP * DIM * INTER];
__device__ f16 g_ew2h[(size_t)N_EXP * INTER * DIM];

__device__ int   g_counts [N_EXP];
__device__ int   g_offsets[N_EXP];
__device__ int   g_cursor [N_EXP];
__device__ int   g_expt_idx[NSLOT];
__device__ float g_expt_w [NSLOT];
__device__ int   g_perm_token[NSLOT];
__device__ float g_perm_w   [NSLOT];
__device__ int   g_slot_of  [NSLOT];

// ---------------- helpers ----------------
__device__ __forceinline__ float blockReduceSum256(float v) {
    __shared__ float red[8];
    int lane = threadIdx.x & 31, warp = threadIdx.x >> 5;
    #pragma unroll
    for (int o = 16; o > 0; o >>= 1) v += __shfl_xor_sync(0xffffffffu, v, o);
    if (lane == 0) red[warp] = v;
    __syncthreads();
    if (warp == 0) {
        v = (lane < 8) ? red[lane] : 0.f;
        #pragma unroll
        for (int o = 4; o > 0; o >>= 1) v += __shfl_xor_sync(0xffffffffu, v, o);
        if (lane == 0) red[0] = v;
    }
    __syncthreads();
    return red[0];
}

__device__ __forceinline__ float blockReduceMax256(float v) {
    __shared__ float red[8];
    int lane = threadIdx.x & 31, warp = threadIdx.x >> 5;
    #pragma unroll
    for (int o = 16; o > 0; o >>= 1) v = fmaxf(v, __shfl_xor_sync(0xffffffffu, v, o));
    if (lane == 0) red[warp] = v;
    __syncthreads();
    if (warp == 0) {
        v = (lane < 8) ? red[lane] : -1e30f;
        #pragma unroll
        for (int o = 4; o > 0; o >>= 1) v = fmaxf(v, __shfl_xor_sync(0xffffffffu, v, o));
        if (lane == 0) red[0] = v;
    }
    __syncthreads();
    return red[0];
}

__device__ __forceinline__ void mma_f16(float* c, const uint32_t* a, const uint32_t* b) {
    asm volatile(
        "mma.sync.aligned.m16n8k16.row.col.f32.f16.f16.f32 "
        "{%0,%1,%2,%3}, {%4,%5,%6,%7}, {%8,%9}, {%0,%1,%2,%3};\n"
        : "+f"(c[0]), "+f"(c[1]), "+f"(c[2]), "+f"(c[3])
        : "r"(a[0]), "r"(a[1]), "r"(a[2]), "r"(a[3]), "r"(b[0]), "r"(b[1]));
}

__device__ __forceinline__ int swA(int row) { return ((row >> 1) & 3) << 2; }
__device__ __forceinline__ int swB(int col) { return (((col >> 1) & 3) << 2) ^ ((col >> 2) & 3); }

__device__ __forceinline__ float silu_f(float a) { return a / (1.f + __expf(-a)); }

// ---------------- fp32 -> fp16 weight conversion ----------------
__global__ void f32tof16_kernel(const float* __restrict__ src, f16* __restrict__ dst, int n4) {
    for (int i = blockIdx.x * blockDim.x + threadIdx.x; i < n4; i += gridDim.x * blockDim.x) {
        float4 v = ((const float4*)src)[i];
        __half2* d = (__half2*)(dst + (size_t)i * 4);
        d[0] = __floats2half2_rn(v.x, v.y);
        d[1] = __floats2half2_rn(v.z, v.w);
    }
}

// ---------------- rmsnorm (float4 vectorized) ----------------
__global__ void rmsnorm_kernel(const float* __restrict__ x, const float* __restrict__ w,
                               float* __restrict__ o32, f16* __restrict__ o16,
                               int D, int in_stride) {
    int t = blockIdx.x;
    const float4* row = (const float4*)(x + (size_t)t * in_stride);
    const float4* wv4 = (const float4*)w;
    int nv = D >> 2;
    float ss = 0.f;
    for (int i = threadIdx.x; i < nv; i += 256) {
        float4 v = row[i];
        ss += v.x * v.x + v.y * v.y + v.z * v.z + v.w * v.w;
    }
    ss = blockReduceSum256(ss);
    __shared__ float inv;
    if (threadIdx.x == 0) inv = rsqrtf(ss / (float)D + EPS);
    __syncthreads();
    float iv = inv;
    for (int i = threadIdx.x; i < nv; i += 256) {
        float4 v = row[i];
        float4 wv = wv4[i];
        float4 r = make_float4(v.x * iv * wv.x, v.y * iv * wv.y,
                               v.z * iv * wv.z, v.w * iv * wv.w);
        if (o32) *(float4*)(o32 + (size_t)t * D + i * 4) = r;
        if (o16) {
            __half2* oh = (__half2*)(o16 + (size_t)t * D + i * 4);
            oh[0] = __floats2half2_rn(r.x, r.y);
            oh[1] = __floats2half2_rn(r.z, r.w);
        }
    }
}

// ---------------- fp16 tensor-core GEMM -----------------------------------
// CTA tile: 128 x (WN*32). MODE 0: dense; MODE 1: A gathered; MODE 2: expert
// offset + perm_w scale. BLAY: 0 = B fp32 [K][N]; 1 = B f16 [K][N]; 2 = B f16 [N][K].
// CBF: C f16. CAUSAL: 0 none; 1 triangular decode; 2 K clip at bm+128.
template<int MODE, int BLAY, bool CBF, int CAUSAL, int WN>
__global__ void __launch_bounds__(256)
gemm_k(const f16* __restrict__ A, const void* __restrict__ Bv, void* __restrict__ Cv,
       const float* __restrict__ resid,
       int M, int N, int K, int lda, int ldb, int ldc, int zdiv,
       long long sA1, long long sA2, long long sB1, long long sB2,
       long long sC1, long long sC2) {
    const int NCOLS = WN * 32;
    __shared__ uint32_t As32[2][2048];
    __shared__ uint32_t Bs32[2][WN * 512];
    __shared__ int stoks[128];

    int tid = threadIdx.x;
    int warp = tid >> 5, lane = tid & 31;
    int g = lane >> 2, tg = lane & 3;
    int wm = warp / WN, wn = warp % WN;
    int m0w = wm * (WN * 16), n0w = wn * 32;

    int bn, bm;
    if (CAUSAL == 1) {
        const int R = 128 / NCOLS;
        int ti = blockIdx.x;
        int bmt = 0;
        while (R * (bmt + 1) * (bmt + 2) / 2 <= ti) bmt++;
        int bnt = ti - R * bmt * (bmt + 1) / 2;
        bm = bmt * 128; bn = bnt * NCOLS;
    } else {
        bn = blockIdx.x * NCOLS;
        bm = blockIdx.y * 128;
    }
    int z = blockIdx.z;
    long long offA = (long long)(z / zdiv) * sA1 + (long long)(z % zdiv) * sA2;
    long long offB = (long long)(z / zdiv) * sB1 + (long long)(z % zdiv) * sB2;
    long long offC = (long long)(z / zdiv) * sC1 + (long long)(z % zdiv) * sC2;

    int cnt = M, base = 0;
    if (MODE != 0) {
        cnt = g_counts[z];
        base = g_offsets[z];
        if (bm >= cnt) return;
    }
    if (MODE == 1) {
        if (tid < 128) stoks[tid] = (bm + tid < cnt) ? g_perm_token[base + bm + tid] : 0;
        __syncthreads();
    }

    const f16* Ap = A + offA;
    const float* Bf = (BLAY == 0) ? ((const float*)Bv + offB) : nullptr;
    const f16*  Bh = (BLAY != 0) ? ((const f16*)Bv + offB) : nullptr;

    int Keff = K;
    if (CAUSAL == 2) { int kl = bm + 128; Keff = kl < K ? kl : K; }

    float cacc[WN][4][4];
    #pragma unroll
    for (int a = 0; a < WN; a++)
        #pragma unroll
        for (int b = 0; b < 4; b++)
            #pragma unroll
            for (int c = 0; c < 4; c++) cacc[a][b][c] = 0.f;

    uint4 rA[2];
    float4 rBf[WN];
    uint4 rBh[WN / 2];

    auto stage = [&](int kk) {
        #pragma unroll
        for (int i = 0; i < 2; i++) {
            int fidx = tid + i * 256;
            int r = fidx >> 2, c8 = fidx & 3;
            uint4 v = make_uint4(0, 0, 0, 0);
            if (MODE == 0) {
                int row = bm + r;
                if (row < M) v = *(const uint4*)(Ap + (size_t)row * lda + kk + c8 * 8);
            } else if (MODE == 1) {
                if (bm + r < cnt) {
                    int tok = stoks[r];
                    v = *(const uint4*)(Ap + (size_t)tok * lda + kk + c8 * 8);
                }
            } else {
                if (bm + r < cnt)
                    v = *(const uint4*)(Ap + (size_t)(base + bm + r) * lda + kk + c8 * 8);
            }
            rA[i] = v;
        }
        if (BLAY == 0) {
            #pragma unroll
            for (int i = 0; i < WN; i++) {
                int fidx = tid + i * 256;
                int r = fidx / (NCOLS / 4), c4 = fidx % (NCOLS / 4);
                int col = bn + c4 * 4;
                float4 v = make_float4(0.f, 0.f, 0.f, 0.f);
                if (col < N) v = *(const float4*)(Bf + (size_t)(kk + r) * ldb + col);
                rBf[i] = v;
            }
        } else if (BLAY == 1) {
            #pragma unroll
            for (int i = 0; i < WN / 2; i++) {
                int fidx = tid + i * 256;
                int r = fidx / (NCOLS / 8), c8 = fidx % (NCOLS / 8);
                int col = bn + c8 * 8;
                uint4 v = make_uint4(0, 0, 0, 0);
                if (col < N) v = *(const uint4*)(Bh + (size_t)(kk + r) * ldb + col);
                rBh[i] = v;
            }
        } else {
            #pragma unroll
            for (int i = 0; i < WN / 2; i++) {
                int fidx = tid + i * 256;
                int r = fidx >> 2, c8 = fidx & 3;
                uint4 v = make_uint4(0, 0, 0, 0);
                if (bn + r < N) v = *(const uint4*)(Bh + (size_t)(bn + r) * ldb + kk + c8 * 8);
                rBh[i] = v;
            }
        }
    };

    auto commit = [&](int buf) {
        #pragma unroll
        for (int i = 0; i < 2; i++) {
            int fidx = tid + i * 256;
            int r = fidx >> 2, c8 = fidx & 3;
            int slotblk = (c8 * 4) ^ swA(r);
            *(uint4*)&As32[buf][r * 16 + slotblk] = rA[i];
        }
        if (BLAY == 0) {
            uint16_t* Bs16 = (uint16_t*)Bs32[buf];
            #pragma unroll
            for (int i = 0; i < WN; i++) {
                int fidx = tid + i * 256;
                int r = fidx / (NCOLS / 4), c4 = fidx % (NCOLS / 4);
                int sig = r >> 1, odd = r & 1;
                float vv[4] = {rBf[i].x, rBf[i].y, rBf[i].z, rBf[i].w};
                #pragma unroll
                for (int j = 0; j < 4; j++) {
                    int col = c4 * 4 + j;
                    f16 hv = __float2half_rn(vv[j]);
                    Bs16[col * 32 + (sig ^ swB(col)) * 2 + odd] = *(uint16_t*)&hv;
                }
            }
        } else if (BLAY == 1) {
            uint16_t* Bs16 = (uint16_t*)Bs32[buf];
            #pragma unroll
            for (int i = 0; i < WN / 2; i++) {
                int fidx = tid + i * 256;
                int r = fidx / (NCOLS / 8), c8 = fidx % (NCOLS / 8);
                int sig = r >> 1, odd = r & 1;
                const uint16_t* src = (const uint16_t*)&rBh[i];
                #pragma unroll
                for (int j = 0; j < 8; j++) {
                    int col = c8 * 8 + j;
                    Bs16[col * 32 + (sig ^ swB(col)) * 2 + odd] = src[j];
                }
            }
        } else {
            #pragma unroll
            for (int i = 0; i < WN / 2; i++) {
                int fidx = tid + i * 256;
                int r = fidx >> 2, c8 = fidx & 3;
                int slotblk = (c8 * 4) ^ swA(r);
                *(uint4*)&Bs32[buf][r * 16 + slotblk] = rBh[i];
            }
        }
    };

    auto compute = [&](int buf) {
        #pragma unroll
        for (int ks = 0; ks < 2; ks++) {
            int sb = ks * 8;
            uint32_t afr[WN][4], bfr[4][2];
            #pragma unroll
            for (int mt = 0; mt < WN; mt++) {
                int r0 = m0w + mt * 16 + g;
                int r1 = r0 + 8;
                afr[mt][0] = As32[buf][r0 * 16 + ((sb + tg) ^ swA(r0))];
                afr[mt][1] = As32[buf][r1 * 16 + ((sb + tg) ^ swA(r1))];
                afr[mt][2] = As32[buf][r0 * 16 + ((sb + tg + 4) ^ swA(r0))];
                afr[mt][3] = As32[buf][r1 * 16 + ((sb + tg + 4) ^ swA(r1))];
            }
            #pragma unroll
            for (int nt = 0; nt < 4; nt++) {
                int c0 = n0w + nt * 8 + g;
                int sw = (BLAY == 2) ? swA(c0) : swB(c0);
                bfr[nt][0] = Bs32[buf][c0 * 16 + ((sb + tg) ^ sw)];
                bfr[nt][1] = Bs32[buf][c0 * 16 + ((sb + tg + 4) ^ sw)];
            }
            #pragma unroll
            for (int mt = 0; mt < WN; mt++)
                #pragma unroll
                for (int nt = 0; nt < 4; nt++)
                    mma_f16(cacc[mt][nt], afr[mt], bfr[nt]);
        }
    };

    stage(0);
    commit(0);
    if (Keff > 32) stage(32);
    __syncthreads();
    int buf = 0;
    for (int kk = 0; kk < Keff; kk += 32) {
        if (kk + 32 < Keff) {
            commit(buf ^ 1);
            if (kk + 64 < Keff) stage(kk + 64);
        }
        compute(buf);
        __syncthreads();
        buf ^= 1;
    }

    float* Cf = (float*)Cv + offC;
    f16* Ch = (f16*)Cv + offC;
    #pragma unroll
    for (int mt = 0; mt < WN; mt++) {
        #pragma unroll
        for (int half_ = 0; half_ < 2; half_++) {
            int lr = bm + m0w + mt * 16 + g + half_ * 8;
            bool rowok = (MODE == 0) ? (lr < M) : (lr < cnt);
            if (!rowok) continue;
            size_t orow = (MODE == 0) ? (size_t)lr : (size_t)(base + lr);
            float scale = (MODE == 2) ? g_perm_w[base + lr] : 1.f;
            #pragma unroll
            for (int nt = 0; nt < 4; nt++) {
                int col = bn + n0w + nt * 8 + 2 * tg;
                if (col >= N) continue;
                float v0 = cacc[mt][nt][half_ * 2 + 0];
                float v1 = cacc[mt][nt][half_ * 2 + 1];
                if (MODE == 2) { v0 *= scale; v1 *= scale; }
                if (CBF) {
                    *(__half2*)(Ch + orow * ldc + col) = __floats2half2_rn(v0, v1);
                } else {
                    if (MODE == 0 && resid) {
                        float2 rv = *(const float2*)(resid + orow * ldc + col);
                        v0 += rv.x; v1 += rv.y;
                    }
                    *(float2*)(Cf + orow * ldc + col) = make_float2(v0, v1);
                }
            }
        }
    }
}

// ---------------- fused gated up-proj: C = silu(A@B1) * (A@B3), f16 out ----
// MODE 0: dense rows; MODE 1: rows gathered (expert z).
// BLAY: 0 = B fp32 [K][N]; 1 = B f16 [K][N].
template<int MODE, int BLAY, int WN>
__global__ void __launch_bounds__(256)
gemm_dual(const f16* __restrict__ A, const void* __restrict__ B1g,
          const void* __restrict__ B3g, f16* __restrict__ C,
          int M, int N, int K, int lda, long long strB) {
    const int NCOLS = WN * 32;
    __shared__ uint32_t As32[2][2048];
    __shared__ uint32_t B1s32[2][WN * 512];
    __shared__ uint32_t B3s32[2][WN * 512];
    __shared__ int stoks[128];

    int tid = threadIdx.x;
    int warp = tid >> 5, lane = tid & 31;
    int g = lane >> 2, tg = lane & 3;
    int wm = warp / WN, wn = warp % WN;
    int m0w = wm * (WN * 16), n0w = wn * 32;

    int bn = blockIdx.x * NCOLS;
    int bm = blockIdx.y * 128;
    int z = blockIdx.z;

    int cnt = M, base = 0;
    if (MODE == 1) {
        cnt = g_counts[z];
        base = g_offsets[z];
        if (bm >= cnt) return;
        if (tid < 128) stoks[tid] = (bm + tid < cnt) ? g_perm_token[base + bm + tid] : 0;
        __syncthreads();
    }
    const float* B1f = (BLAY == 0) ? ((const float*)B1g + (long long)z * strB) : nullptr;
    const float* B3f = (BLAY == 0) ? ((const float*)B3g + (long long)z * strB) : nullptr;
    const f16* B1h = (BLAY == 1) ? ((const f16*)B1g + (long long)z * strB) : nullptr;
    const f16* B3h = (BLAY == 1) ? ((const f16*)B3g + (long long)z * strB) : nullptr;

    float acc1[WN][4][4], acc3[WN][4][4];
    #pragma unroll
    for (int a = 0; a < WN; a++)
        #pragma unroll
        for (int b = 0; b < 4; b++)
            #pragma unroll
            for (int c = 0; c < 4; c++) { acc1[a][b][c] = 0.f; acc3[a][b][c] = 0.f; }

    uint4 rA[2];
    float4 rB1f[WN], rB3f[WN];
    uint4 rB1h[WN / 2], rB3h[WN / 2];

    auto stage = [&](int kk) {
        #pragma unroll
        for (int i = 0; i < 2; i++) {
            int fidx = tid + i * 256;
            int r = fidx >> 2, c8 = fidx & 3;
            uint4 v = make_uint4(0, 0, 0, 0);
            if (MODE == 0) {
                if (bm + r < M) v = *(const uint4*)(A + (size_t)(bm + r) * lda + kk + c8 * 8);
            } else {
                if (bm + r < cnt) {
                    int tok = stoks[r];
                    v = *(const uint4*)(A + (size_t)tok * lda + kk + c8 * 8);
                }
            }
            rA[i] = v;
        }
        if (BLAY == 0) {
            #pragma unroll
            for (int i = 0; i < WN; i++) {
                int fidx = tid + i * 256;
                int r = fidx / (NCOLS / 4), c4 = fidx % (NCOLS / 4);
                int col = bn + c4 * 4;
                float4 v1 = make_float4(0.f, 0.f, 0.f, 0.f);
                float4 v3 = v1;
                if (col < N) {
                    v1 = *(const float4*)(B1f + (size_t)(kk + r) * N + col);
                    v3 = *(const float4*)(B3f + (size_t)(kk + r) * N + col);
                }
                rB1f[i] = v1; rB3f[i] = v3;
            }
        } else {
            #pragma unroll
            for (int i = 0; i < WN / 2; i++) {
                int fidx = tid + i * 256;
                int r = fidx / (NCOLS / 8), c8 = fidx % (NCOLS / 8);
                int col = bn + c8 * 8;
                uint4 v1 = make_uint4(0, 0, 0, 0), v3 = v1;
                if (col < N) {
                    v1 = *(const uint4*)(B1h + (size_t)(kk + r) * N + col);
                    v3 = *(const uint4*)(B3h + (size_t)(kk + r) * N + col);
                }
                rB1h[i] = v1; rB3h[i] = v3;
            }
        }
    };

    auto commit = [&](int buf) {
        #pragma unroll
        for (int i = 0; i < 2; i++) {
            int fidx = tid + i * 256;
            int r = fidx >> 2, c8 = fidx & 3;
            int slotblk = (c8 * 4) ^ swA(r);
            *(uint4*)&As32[buf][r * 16 + slotblk] = rA[i];
        }
        uint16_t* b1 = (uint16_t*)B1s32[buf];
        uint16_t* b3 = (uint16_t*)B3s32[buf];
        if (BLAY == 0) {
            #pragma unroll
            for (int i = 0; i < WN; i++) {
                int fidx = tid + i * 256;
                int r = fidx / (NCOLS / 4), c4 = fidx % (NCOLS / 4);
                int sig = r >> 1, odd = r & 1;
                float w1[4] = {rB1f[i].x, rB1f[i].y, rB1f[i].z, rB1f[i].w};
                float w3[4] = {rB3f[i].x, rB3f[i].y, rB3f[i].z, rB3f[i].w};
                #pragma unroll
                for (int j = 0; j < 4; j++) {
                    int col = c4 * 4 + j;
                    int slot = (sig ^ swB(col)) * 2 + odd;
                    f16 h1 = __float2half_rn(w1[j]);
                    f16 h3 = __float2half_rn(w3[j]);
                    b1[col * 32 + slot] = *(uint16_t*)&h1;
                    b3[col * 32 + slot] = *(uint16_t*)&h3;
                }
            }
        } else {
            #pragma unroll
            for (int i = 0; i < WN / 2; i++) {
                int fidx = tid + i * 256;
                int r = fidx / (NCOLS / 8), c8 = fidx % (NCOLS / 8);
                int sig = r >> 1, odd = r & 1;
                const uint16_t* s1p = (const uint16_t*)&rB1h[i];
                const uint16_t* s3p = (const uint16_t*)&rB3h[i];
                #pragma unroll
                for (int j = 0; j < 8; j++) {
                    int col = c8 * 8 + j;
                    int slot = (sig ^ swB(col)) * 2 + odd;
                    b1[col * 32 + slot] = s1p[j];
                    b3[col * 32 + slot] = s3p[j];
                }
            }
        }
    };

    auto compute = [&](int buf) {
        #pragma unroll
        for (int ks = 0; ks < 2; ks++) {
            int sb = ks * 8;
            uint32_t afr[WN][4], b1fr[4][2], b3fr[4][2];
            #pragma unroll
            for (int mt = 0; mt < WN; mt++) {
                int r0 = m0w + mt * 16 + g;
                int r1 = r0 + 8;
                afr[mt][0] = As32[buf][r0 * 16 + ((sb + tg) ^ swA(r0))];
                afr[mt][1] = As32[buf][r1 * 16 + ((sb + tg) ^ swA(r1))];
                afr[mt][2] = As32[buf][r0 * 16 + ((sb + tg + 4) ^ swA(r0))];
                afr[mt][3] = As32[buf][r1 * 16 + ((sb + tg + 4) ^ swA(r1))];
            }
            #pragma unroll
            for (int nt = 0; nt < 4; nt++) {
                int c0 = n0w + nt * 8 + g;
                int sw = swB(c0);
                b1fr[nt][0] = B1s32[buf][c0 * 16 + ((sb + tg) ^ sw)];
                b1fr[nt][1] = B1s32[buf][c0 * 16 + ((sb + tg + 4) ^ sw)];
                b3fr[nt][0] = B3s32[buf][c0 * 16 + ((sb + tg) ^ sw)];
                b3fr[nt][1] = B3s32[buf][c0 * 16 + ((sb + tg + 4) ^ sw)];
            }
            #pragma unroll
            for (int mt = 0; mt < WN; mt++)
                #pragma unroll
                for (int nt = 0; nt < 4; nt++) {
                    mma_f16(acc1[mt][nt], afr[mt], b1fr[nt]);
                    mma_f16(acc3[mt][nt], afr[mt], b3fr[nt]);
                }
        }
    };

    stage(0);
    commit(0);
    if (K > 32) stage(32);
    __syncthreads();
    int buf = 0;
    for (int kk = 0; kk < K; kk += 32) {
        if (kk + 32 < K) {
            commit(buf ^ 1);
            if (kk + 64 < K) stage(kk + 64);
        }
        compute(buf);
        __syncthreads();
        buf ^= 1;
    }

    #pragma unroll
    for (int mt = 0; mt < WN; mt++) {
        #pragma unroll
        for (int half_ = 0; half_ < 2; half_++) {
            int lr = bm + m0w + mt * 16 + g + half_ * 8;
            bool rowok = (MODE == 0) ? (lr < M) : (lr < cnt);
            if (!rowok) continue;
            size_t orow = (MODE == 0) ? (size_t)lr : (size_t)(base + lr);
            #pragma unroll
            for (int nt = 0; nt < 4; nt++) {
                int col = bn + n0w + nt * 8 + 2 * tg;
                if (col >= N) continue;
                float a0 = acc1[mt][nt][half_ * 2 + 0];
                float a1 = acc1[mt][nt][half_ * 2 + 1];
                float b0 = acc3[mt][nt][half_ * 2 + 0];
                float b1 = acc3[mt][nt][half_ * 2 + 1];
                *(__half2*)(C + orow * N + col) =
                    __floats2half2_rn(silu_f(a0) * b0, silu_f(a1) * b1);
            }
        }
    }
}

// ---------------- pack per-head K ----------------
__global__ void prep_k_kernel(const f16* __restrict__ kvph, const float* __restrict__ kvF,
                              f16* __restrict__ kh) {
    long long i = (long long)blockIdx.x * 256 + threadIdx.x;
    if (i >= (long long)BH * SEQ * QK_HD) return;
    int d = (int)(i & 127);
    long long zs = i >> 7;
    int s = (int)(zs & (SEQ - 1));
    int zz = (int)(zs >> 10);
    int h = zz & 7, b = zz >> 3;
    size_t t = (size_t)b * SEQ + s;
    f16 val;
    if (d < NOPE) val = kvph[t * KVB_N + h * (NOPE + V_HD) + d];
    else          val = __float2half_rn(kvF[t * KVA_N + KV_LORA + (d - NOPE)]);
    kh[i] = val;
}

// ---------------- causal softmax (f16 in-place) ----------------
__global__ void softmax_kernel(f16* __restrict__ Ph) {
    int r = blockIdx.x;
    long long zoff = (long long)blockIdx.y * SEQ * SEQ + (long long)r * SEQ;
    f16* row = Ph + zoff;
    int n = r + 1;
    int tid = threadIdx.x;
    float v[4];
    float m = -1e30f;
    #pragma unroll
    for (int j = 0; j < 4; j++) {
        int c = tid + j * 256;
        v[j] = (c < n) ? __half2float(row[c]) : -1e30f;
        m = fmaxf(m, v[j]);
    }
    m = blockReduceMax256(m);
    float e[4], l = 0.f;
    #pragma unroll
    for (int j = 0; j < 4; j++) {
        int c = tid + j * 256;
        e[j] = (c < n) ? __expf(ATTN_SCALE * (v[j] - m)) : 0.f;
        l += e[j];
    }
    l = blockReduceSum256(l);
    float inv = 1.f / l;
    #pragma unroll
    for (int j = 0; j < 4; j++) {
        int c = tid + j * 256;
        row[c] = __float2half_rn(e[j] * inv);
    }
}

// ---------------- gate / routing ----------------
__global__ void zero_counts_kernel() {
    if (threadIdx.x < N_EXP) g_counts[threadIdx.x] = 0;
}

__global__ void gate_kernel(const float* __restrict__ xf, const float* __restrict__ gw,
                            const float* __restrict__ gb) {
    int t = blockIdx.x;
    __shared__ float sscore[N_EXP];
    int tid = threadIdx.x, warp = tid >> 5, lane = tid & 31;
    for (int e = warp; e < N_EXP; e += 4) {
        float s = 0.f;
        for (int d = lane; d < DIM; d += 32) s += xf[(size_t)t * DIM + d] * gw[(size_t)e * DIM + d];
        #pragma unroll
        for (int o = 16; o > 0; o >>= 1) s += __shfl_xor_sync(0xffffffffu, s, o);
        if (lane == 0) sscore[e] = 1.f / (1.f + expf(-s));
    }
    __syncthreads();
    if (tid == 0) {
        float orig[N_EXP], s[N_EXP];
        for (int e = 0; e < N_EXP; e++) { orig[e] = sscore[e]; s[e] = orig[e] + gb[e]; }
        float gs[N_GROUPS];
        for (int gg = 0; gg < N_GROUPS; gg++) {
            float m1 = -1e30f, m2 = -1e30f;
            for (int k = 0; k < 4; k++) {
                float v = s[gg * 4 + k];
                if (v > m1) { m2 = m1; m1 = v; } else if (v > m2) m2 = v;
            }
            gs[gg] = m1 + m2;
        }
        bool gsel[N_GROUPS] = {};
        for (int r = 0; r < TOPK_G; r++) {
            int best = -1; float bv = -1e30f;
            for (int gg = 0; gg < N_GROUPS; gg++)
                if (!gsel[gg] && gs[gg] > bv) { bv = gs[gg]; best = gg; }
            gsel[best] = true;
        }
        for (int gg = 0; gg < N_GROUPS; gg++)
            if (!gsel[gg]) for (int k = 0; k < 4; k++) s[gg * 4 + k] = -1e30f;
        int idx[TOPK]; bool used[N_EXP] = {};
        for (int r = 0; r < TOPK; r++) {
            int best = -1; float bv = -2e30f;
            for (int e = 0; e < N_EXP; e++)
                if (!used[e] && s[e] > bv) { bv = s[e]; best = e; }
            used[best] = true; idx[r] = best;
        }
        float wsum = 0.f;
        for (int r = 0; r < TOPK; r++) wsum += orig[idx[r]];
        float inv = 1.f / (wsum + 1e-20f);
        for (int r = 0; r < TOPK; r++) {
            g_expt_idx[t * TOPK + r] = idx[r];
            g_expt_w[t * TOPK + r] = orig[idx[r]] * inv;
            atomicAdd(&g_counts[idx[r]], 1);
        }
    }
}

__global__ void offsets_kernel() {
    if (threadIdx.x == 0) {
        int acc = 0;
        for (int e = 0; e < N_EXP; e++) {
            g_offsets[e] = acc;
            g_cursor[e] = acc;
            acc += g_counts[e];
        }
    }
}

__global__ void scatter_kernel() {
    int i = blockIdx.x * blockDim.x + threadIdx.x;
    if (i < NSLOT) {
        int e = g_expt_idx[i];
        int pos = atomicAdd(&g_cursor[e], 1);
        g_perm_token[pos] = i >> 2;
        g_perm_w[pos] = g_expt_w[i];
        g_slot_of[i] = pos;
    }
}

// ---------------- final combine (float4) ----------------
__global__ void final_kernel(float* __restrict__ out) {
    int t = blockIdx.x;
    int s0 = g_slot_of[t * 4 + 0], s1 = g_slot_of[t * 4 + 1];
    int s2 = g_slot_of[t * 4 + 2], s3 = g_slot_of[t * 4 + 3];
    int i = threadIdx.x;
    const float4* x2v = (const float4*)(g_x2 + (size_t)t * DIM);
    const float4* zbv = (const float4*)(g_zb + (size_t)t * DIM);
    const float4* y0 = (const float4*)(g_ybuf + (size_t)s0 * DIM);
    const float4* y1 = (const float4*)(g_ybuf + (size_t)s1 * DIM);
    const float4* y2 = (const float4*)(g_ybuf + (size_t)s2 * DIM);
    const float4* y3 = (const float4*)(g_ybuf + (size_t)s3 * DIM);
    float4 a = x2v[i], b = zbv[i], c0 = y0[i], c1 = y1[i], c2 = y2[i], c3 = y3[i];
    float4 r = make_float4(a.x + b.x + c0.x + c1.x + c2.x + c3.x,
                           a.y + b.y + c0.y + c1.y + c2.y + c3.y,
                           a.z + b.z + c0.z + c1.z + c2.z + c3.z,
                           a.w + b.w + c0.w + c1.w + c2.w + c3.w);
    *(float4*)(out + (size_t)t * DIM + i * 4) = r;
}

// ---------------- launcher ----------------
extern "C" void kernel_launch(void* const* d_in, const int* in_sizes, int n_in,
                              void* d_out, int out_size) {
    const float* x       = (const float*)d_in[0];
    const float* norm_a  = (const float*)d_in[1];
    const float* wq      = (const float*)d_in[2];
    const float* wkv_a   = (const float*)d_in[3];
    const float* kvnw    = (const float*)d_in[4];
    const float* wkv_b   = (const float*)d_in[5];
    const float* wo      = (const float*)d_in[6];
    const float* norm_m  = (const float*)d_in[7];
    const float* gate_w  = (const float*)d_in[8];
    const float* gate_b  = (const float*)d_in[9];
    const float* ew1     = (const float*)d_in[10];
    const float* ew2     = (const float*)d_in[11];
    const float* ew3     = (const float*)d_in[12];
    const float* sw1     = (const float*)d_in[13];
    const float* sw2     = (const float*)d_in[14];
    const float* sw3     = (const float*)d_in[15];
    float* out = (float*)d_out;

    float *kvF, *x2, *xf, *ybuf, *zb;
    f16 *x1h, *qh, *cnh, *kvph, *khh, *Ph, *attnh, *xfh, *hbufh, *hsh;
    f16 *ew1h, *ew3h, *ew2h;
    cudaGetSymbolAddress((void**)&kvF, g_kvF);
    cudaGetSymbolAddress((void**)&x2,  g_x2);
    cudaGetSymbolAddress((void**)&xf,  g_xf);
    cudaGetSymbolAddress((void**)&ybuf,g_ybuf);
    cudaGetSymbolAddress((void**)&zb,  g_zb);
    cudaGetSymbolAddress((void**)&x1h, g_x1h);
    cudaGetSymbolAddress((void**)&qh,  g_qh);
    cudaGetSymbolAddress((void**)&cnh, g_cnh);
    cudaGetSymbolAddress((void**)&kvph,g_kvph);
    cudaGetSymbolAddress((void**)&khh, g_khh);
    cudaGetSymbolAddress((void**)&Ph,  g_Ph);
    cudaGetSymbolAddress((void**)&attnh, g_attnh);
    cudaGetSymbolAddress((void**)&xfh, g_xfh);
    cudaGetSymbolAddress((void**)&hbufh, g_hbufh);
    cudaGetSymbolAddress((void**)&hsh, g_hsh);
    cudaGetSymbolAddress((void**)&ew1h, g_ew1h);
    cudaGetSymbolAddress((void**)&ew3h, g_ew3h);
    cudaGetSymbolAddress((void**)&ew2h, g_ew2h);

    static cudaStream_t s1 = nullptr, s2 = nullptr;
    static cudaEvent_t evF0, evF1, evJ1, evF2, evJ2, evConv;
    if (!s1) {
        cudaStreamCreateWithFlags(&s1, cudaStreamNonBlocking);
        cudaStreamCreateWithFlags(&s2, cudaStreamNonBlocking);
        cudaEventCreateWithFlags(&evF0, cudaEventDisableTiming);
        cudaEventCreateWithFlags(&evF1, cudaEventDisableTiming);
        cudaEventCreateWithFlags(&evJ1, cudaEventDisableTiming);
        cudaEventCreateWithFlags(&evF2, cudaEventDisableTiming);
        cudaEventCreateWithFlags(&evJ2, cudaEventDisableTiming);
        cudaEventCreateWithFlags(&evConv, cudaEventDisableTiming);
    }

    const int NW4 = N_EXP * DIM * INTER / 4;   // float4 count per expert weight tensor

    // ---- fork 0: expert-weight fp16 conversion on s1 (no data deps) ----
    cudaEventRecord(evF0, 0);
    cudaStreamWaitEvent(s1, evF0, 0);
    f32tof16_kernel<<<4096, 256, 0, s1>>>(ew1, ew1h, NW4);
    f32tof16_kernel<<<4096, 256, 0, s1>>>(ew3, ew3h, NW4);
    f32tof16_kernel<<<4096, 256, 0, s1>>>(ew2, ew2h, NW4);
    cudaEventRecord(evConv, s1);

    // 1) attention input norm -> fp16
    rmsnorm_kernel<<<TTOK, 256>>>(x, norm_a, nullptr, x1h, DIM, DIM);

    // ---- fork 1: q-proj on s2, kv chain on main ----
    cudaEventRecord(evF1, 0);
    cudaStreamWaitEvent(s2, evF1, 0);
    gemm_k<0,0,true,0,2><<<dim3(16,16,1), 256, 0, s2>>>(x1h, wq, qh, nullptr,
        TTOK, DIM, DIM, DIM, DIM, DIM, 1, 0,0,0,0,0,0);
    gemm_k<0,0,false,0,2><<<dim3(5,16,1), 256>>>(x1h, wkv_a, kvF, nullptr,
        TTOK, KVA_N, DIM, DIM, KVA_N, KVA_N, 1, 0,0,0,0,0,0);
    rmsnorm_kernel<<<TTOK, 256>>>(kvF, kvnw, nullptr, cnh, KV_LORA, KVA_N);
    gemm_k<0,0,true,0,2><<<dim3(24,16,1), 256>>>(cnh, wkv_b, kvph, nullptr,
        TTOK, KVB_N, KV_LORA, KV_LORA, KVB_N, KVB_N, 1, 0,0,0,0,0,0);
    prep_k_kernel<<<(int)(((long long)BH*SEQ*QK_HD + 255)/256), 256>>>(kvph, kvF, khh);
    cudaEventRecord(evJ1, s2);
    cudaStreamWaitEvent(0, evJ1, 0);

    // 7) scores = q @ kh^T, triangular 128x64 tiles, f16 output into Ph
    gemm_k<0,2,true,1,2><<<dim3(72,1,BH), 256>>>(qh, khh, Ph, nullptr,
        SEQ, SEQ, QK_HD, DIM, QK_HD, SEQ, HEADS,
        (long long)SEQ*DIM, 128,
        (long long)HEADS*SEQ*QK_HD, (long long)SEQ*QK_HD,
        (long long)HEADS*SEQ*SEQ, (long long)SEQ*SEQ);
    // 8) causal softmax in-place on Ph
    softmax_kernel<<<dim3(SEQ, BH), 256>>>(Ph);
    // 9) attn = P @ V
    gemm_k<0,1,true,2,2><<<dim3(2,8,BH), 256>>>(Ph, kvph + NOPE, attnh, nullptr,
        SEQ, V_HD, SEQ, SEQ, KVB_N, DIM, HEADS,
        (long long)HEADS*SEQ*SEQ, (long long)SEQ*SEQ,
        (long long)SEQ*KVB_N, (long long)(NOPE+V_HD),
        (long long)SEQ*DIM, 128);
    // 10) x2 = x + attn @ wo
    gemm_k<0,0,false,0,2><<<dim3(16,16,1), 256>>>(attnh, wo, x2, x,
        TTOK, DIM, DIM, DIM, DIM, DIM, 1, 0,0,0,0,0,0);
    // 11) moe input norm
    rmsnorm_kernel<<<TTOK, 256>>>(x2, norm_m, xf, xfh, DIM, DIM);

    // ---- fork 2: shared expert on s2, routing + routed experts on main ----
    cudaEventRecord(evF2, 0);
    cudaStreamWaitEvent(s2, evF2, 0);
    gemm_dual<0,0,2><<<dim3(8,16,1), 256, 0, s2>>>(xfh, sw1, sw3, hsh,
        TTOK, INTER, DIM, DIM, 0);
    gemm_k<0,0,false,0,2><<<dim3(16,16,1), 256, 0, s2>>>(hsh, sw2, zb, nullptr,
        TTOK, DIM, INTER, INTER, DIM, DIM, 1, 0,0,0,0,0,0);
    cudaEventRecord(evJ2, s2);

    // 12) gate + routing (main)
    zero_counts_kernel<<<1, 32>>>();
    gate_kernel<<<TTOK, 128>>>(xf, gate_w, gate_b);
    offsets_kernel<<<1, 32>>>();
    scatter_kernel<<<NSLOT/256, 256>>>();
    // 13) routed experts with f16 weights (wait for conversion)
    cudaStreamWaitEvent(0, evConv, 0);
    gemm_dual<1,1,2><<<dim3(8,16,N_EXP), 256>>>(xfh, ew1h, ew3h, hbufh,
        0, INTER, DIM, DIM, (long long)DIM*INTER);
    gemm_k<2,1,false,0,2><<<dim3(16,16,N_EXP), 256>>>(hbufh, ew2h, ybuf, nullptr,
        0, DIM, INTER, INTER, DIM, DIM, 1, 0,0, (long long)INTER*DIM,0, 0,0);
    // join shared expert before final
    cudaStreamWaitEvent(0, evJ2, 0);

    // 15) final combine
    final_kernel<<<TTOK, 256>>>(out);
}

// round 13
// speedup vs baseline: 1.0472x; 1.0472x over previous
#include <cuda_runtime.h>
#include <cuda_fp16.h>
#include <math.h>
#include <stdint.h>

// ---------------- problem constants ----------------
#define TTOK   2048
#define BATCH  2
#define SEQ    1024
#define DIM    1024
#define HEADS  8
#define BH     16
#define QK_HD  128
#define V_HD   128
#define NOPE   64
#define ROPE   64
#define KV_LORA 256
#define KVA_N  320
#define KVB_N  1536
#define N_EXP  32
#define N_GROUPS 8
#define TOPK   4
#define TOPK_G 4
#define INTER  512
#define NSLOT  8192
#define EPS    1e-6f
#define ATTN_SCALE 0.08838834764831843f

typedef __half f16;

// ---------------- scratch ----------------
__device__ float g_kvF [TTOK * KVA_N];
__device__ float g_x2  [TTOK * DIM];
__device__ float g_xf  [TTOK * DIM];
__device__ float g_ybuf[NSLOT * DIM];
__device__ float g_zb  [TTOK * DIM];

__device__ f16 g_x1h [TTOK * DIM];
__device__ f16 g_qh  [TTOK * DIM];
__device__ f16 g_cnh [TTOK * KV_LORA];
__device__ f16 g_kvph[TTOK * KVB_N];
__device__ f16 g_khh [(size_t)BH * SEQ * QK_HD];
__device__ f16 g_Ph  [(size_t)BH * SEQ * SEQ];   // f16 scores -> softmaxed in place
__device__ f16 g_attnh[TTOK * DIM];
__device__ f16 g_xfh [TTOK * DIM];
__device__ f16 g_hbufh[NSLOT * INTER];
__device__ f16 g_hsh [TTOK * INTER];

__device__ int   g_counts [N_EXP];
__device__ int   g_offsets[N_EXP];
__device__ int   g_cursor [N_EXP];
__device__ int   g_expt_idx[NSLOT];
__device__ float g_expt_w [NSLOT];
__device__ int   g_perm_token[NSLOT];
__device__ float g_perm_w   [NSLOT];
__device__ int   g_slot_of  [NSLOT];

// ---------------- helpers ----------------
__device__ __forceinline__ float blockReduceSum256(float v) {
    __shared__ float red[8];
    int lane = threadIdx.x & 31, warp = threadIdx.x >> 5;
    #pragma unroll
    for (int o = 16; o > 0; o >>= 1) v += __shfl_xor_sync(0xffffffffu, v, o);
    if (lane == 0) red[warp] = v;
    __syncthreads();
    if (warp == 0) {
        v = (lane < 8) ? red[lane] : 0.f;
        #pragma unroll
        for (int o = 4; o > 0; o >>= 1) v += __shfl_xor_sync(0xffffffffu, v, o);
        if (lane == 0) red[0] = v;
    }
    __syncthreads();
    return red[0];
}

__device__ __forceinline__ float blockReduceMax256(float v) {
    __shared__ float red[8];
    int lane = threadIdx.x & 31, warp = threadIdx.x >> 5;
    #pragma unroll
    for (int o = 16; o > 0; o >>= 1) v = fmaxf(v, __shfl_xor_sync(0xffffffffu, v, o));
    if (lane == 0) red[warp] = v;
    __syncthreads();
    if (warp == 0) {
        v = (lane < 8) ? red[lane] : -1e30f;
        #pragma unroll
        for (int o = 4; o > 0; o >>= 1) v = fmaxf(v, __shfl_xor_sync(0xffffffffu, v, o));
        if (lane == 0) red[0] = v;
    }
    __syncthreads();
    return red[0];
}

__device__ __forceinline__ void mma_f16(float* c, const uint32_t* a, const uint32_t* b) {
    asm volatile(
        "mma.sync.aligned.m16n8k16.row.col.f32.f16.f16.f32 "
        "{%0,%1,%2,%3}, {%4,%5,%6,%7}, {%8,%9}, {%0,%1,%2,%3};\n"
        : "+f"(c[0]), "+f"(c[1]), "+f"(c[2]), "+f"(c[3])
        : "r"(a[0]), "r"(a[1]), "r"(a[2]), "r"(a[3]), "r"(b[0]), "r"(b[1]));
}

__device__ __forceinline__ int swA(int row) { return ((row >> 1) & 3) << 2; }
__device__ __forceinline__ int swB(int col) { return (((col >> 1) & 3) << 2) ^ ((col >> 2) & 3); }

__device__ __forceinline__ float silu_f(float a) { return a / (1.f + __expf(-a)); }

// ---------------- rmsnorm (float4 vectorized) ----------------
__global__ void rmsnorm_kernel(const float* __restrict__ x, const float* __restrict__ w,
                               float* __restrict__ o32, f16* __restrict__ o16,
                               int D, int in_stride) {
    int t = blockIdx.x;
    const float4* row = (const float4*)(x + (size_t)t * in_stride);
    const float4* wv4 = (const float4*)w;
    int nv = D >> 2;
    float ss = 0.f;
    for (int i = threadIdx.x; i < nv; i += 256) {
        float4 v = row[i];
        ss += v.x * v.x + v.y * v.y + v.z * v.z + v.w * v.w;
    }
    ss = blockReduceSum256(ss);
    __shared__ float inv;
    if (threadIdx.x == 0) inv = rsqrtf(ss / (float)D + EPS);
    __syncthreads();
    float iv = inv;
    for (int i = threadIdx.x; i < nv; i += 256) {
        float4 v = row[i];
        float4 wv = wv4[i];
        float4 r = make_float4(v.x * iv * wv.x, v.y * iv * wv.y,
                               v.z * iv * wv.z, v.w * iv * wv.w);
        if (o32) *(float4*)(o32 + (size_t)t * D + i * 4) = r;
        if (o16) {
            __half2* oh = (__half2*)(o16 + (size_t)t * D + i * 4);
            oh[0] = __floats2half2_rn(r.x, r.y);
            oh[1] = __floats2half2_rn(r.z, r.w);
        }
    }
}

// ---------------- fp16 tensor-core GEMM -----------------------------------
// CTA tile: 128 x (WN*32). MODE 0: dense; MODE 1: A gathered; MODE 2: expert
// offset + perm_w scale. BLAY: 0 = B fp32 [K][N]; 1 = B f16 [K][N]; 2 = B f16 [N][K].
// CBF: C f16. CAUSAL: 0 none; 1 triangular decode; 2 K clip at bm+128.
template<int MODE, int BLAY, bool CBF, int CAUSAL, int WN>
__global__ void __launch_bounds__(256)
gemm_k(const f16* __restrict__ A, const void* __restrict__ Bv, void* __restrict__ Cv,
       const float* __restrict__ resid,
       int M, int N, int K, int lda, int ldb, int ldc, int zdiv,
       long long sA1, long long sA2, long long sB1, long long sB2,
       long long sC1, long long sC2) {
    const int NCOLS = WN * 32;
    __shared__ uint32_t As32[2][2048];
    __shared__ uint32_t Bs32[2][WN * 512];
    __shared__ int stoks[128];

    int tid = threadIdx.x;
    int warp = tid >> 5, lane = tid & 31;
    int g = lane >> 2, tg = lane & 3;
    int wm = warp / WN, wn = warp % WN;
    int m0w = wm * (WN * 16), n0w = wn * 32;

    int bn, bm;
    if (CAUSAL == 1) {
        const int R = 128 / NCOLS;
        int ti = blockIdx.x;
        int bmt = 0;
        while (R * (bmt + 1) * (bmt + 2) / 2 <= ti) bmt++;
        int bnt = ti - R * bmt * (bmt + 1) / 2;
        bm = bmt * 128; bn = bnt * NCOLS;
    } else {
        bn = blockIdx.x * NCOLS;
        bm = blockIdx.y * 128;
    }
    int z = blockIdx.z;
    long long offA = (long long)(z / zdiv) * sA1 + (long long)(z % zdiv) * sA2;
    long long offB = (long long)(z / zdiv) * sB1 + (long long)(z % zdiv) * sB2;
    long long offC = (long long)(z / zdiv) * sC1 + (long long)(z % zdiv) * sC2;

    int cnt = M, base = 0;
    if (MODE != 0) {
        cnt = g_counts[z];
        base = g_offsets[z];
        if (bm >= cnt) return;
    }
    if (MODE == 1) {
        if (tid < 128) stoks[tid] = (bm + tid < cnt) ? g_perm_token[base + bm + tid] : 0;
        __syncthreads();
    }

    const f16* Ap = A + offA;
    const float* Bf = (BLAY == 0) ? ((const float*)Bv + offB) : nullptr;
    const f16*  Bh = (BLAY != 0) ? ((const f16*)Bv + offB) : nullptr;

    int Keff = K;
    if (CAUSAL == 2) { int kl = bm + 128; Keff = kl < K ? kl : K; }

    float cacc[WN][4][4];
    #pragma unroll
    for (int a = 0; a < WN; a++)
        #pragma unroll
        for (int b = 0; b < 4; b++)
            #pragma unroll
            for (int c = 0; c < 4; c++) cacc[a][b][c] = 0.f;

    uint4 rA[2];
    float4 rBf[WN];
    uint4 rBh[WN / 2];

    auto stage = [&](int kk) {
        #pragma unroll
        for (int i = 0; i < 2; i++) {
            int fidx = tid + i * 256;
            int r = fidx >> 2, c8 = fidx & 3;
            uint4 v = make_uint4(0, 0, 0, 0);
            if (MODE == 0) {
                int row = bm + r;
                if (row < M) v = *(const uint4*)(Ap + (size_t)row * lda + kk + c8 * 8);
            } else if (MODE == 1) {
                if (bm + r < cnt) {
                    int tok = stoks[r];
                    v = *(const uint4*)(Ap + (size_t)tok * lda + kk + c8 * 8);
                }
            } else {
                if (bm + r < cnt)
                    v = *(const uint4*)(Ap + (size_t)(base + bm + r) * lda + kk + c8 * 8);
            }
            rA[i] = v;
        }
        if (BLAY == 0) {
            #pragma unroll
            for (int i = 0; i < WN; i++) {
                int fidx = tid + i * 256;
                int r = fidx / (NCOLS / 4), c4 = fidx % (NCOLS / 4);
                int col = bn + c4 * 4;
                float4 v = make_float4(0.f, 0.f, 0.f, 0.f);
                if (col < N) v = *(const float4*)(Bf + (size_t)(kk + r) * ldb + col);
                rBf[i] = v;
            }
        } else if (BLAY == 1) {
            #pragma unroll
            for (int i = 0; i < WN / 2; i++) {
                int fidx = tid + i * 256;
                int r = fidx / (NCOLS / 8), c8 = fidx % (NCOLS / 8);
                int col = bn + c8 * 8;
                uint4 v = make_uint4(0, 0, 0, 0);
                if (col < N) v = *(const uint4*)(Bh + (size_t)(kk + r) * ldb + col);
                rBh[i] = v;
            }
        } else {
            #pragma unroll
            for (int i = 0; i < WN / 2; i++) {
                int fidx = tid + i * 256;
                int r = fidx >> 2, c8 = fidx & 3;
                uint4 v = make_uint4(0, 0, 0, 0);
                if (bn + r < N) v = *(const uint4*)(Bh + (size_t)(bn + r) * ldb + kk + c8 * 8);
                rBh[i] = v;
            }
        }
    };

    auto commit = [&](int buf) {
        #pragma unroll
        for (int i = 0; i < 2; i++) {
            int fidx = tid + i * 256;
            int r = fidx >> 2, c8 = fidx & 3;
            int slotblk = (c8 * 4) ^ swA(r);
            *(uint4*)&As32[buf][r * 16 + slotblk] = rA[i];
        }
        if (BLAY == 0) {
            uint16_t* Bs16 = (uint16_t*)Bs32[buf];
            #pragma unroll
            for (int i = 0; i < WN; i++) {
                int fidx = tid + i * 256;
                int r = fidx / (NCOLS / 4), c4 = fidx % (NCOLS / 4);
                int sig = r >> 1, odd = r & 1;
                float vv[4] = {rBf[i].x, rBf[i].y, rBf[i].z, rBf[i].w};
                #pragma unroll
                for (int j = 0; j < 4; j++) {
                    int col = c4 * 4 + j;
                    f16 hv = __float2half_rn(vv[j]);
                    Bs16[col * 32 + (sig ^ swB(col)) * 2 + odd] = *(uint16_t*)&hv;
                }
            }
        } else if (BLAY == 1) {
            uint16_t* Bs16 = (uint16_t*)Bs32[buf];
            #pragma unroll
            for (int i = 0; i < WN / 2; i++) {
                int fidx = tid + i * 256;
                int r = fidx / (NCOLS / 8), c8 = fidx % (NCOLS / 8);
                int sig = r >> 1, odd = r & 1;
                const uint16_t* src = (const uint16_t*)&rBh[i];
                #pragma unroll
                for (int j = 0; j < 8; j++) {
                    int col = c8 * 8 + j;
                    Bs16[col * 32 + (sig ^ swB(col)) * 2 + odd] = src[j];
                }
            }
        } else {
            #pragma unroll
            for (int i = 0; i < WN / 2; i++) {
                int fidx = tid + i * 256;
                int r = fidx >> 2, c8 = fidx & 3;
                int slotblk = (c8 * 4) ^ swA(r);
                *(uint4*)&Bs32[buf][r * 16 + slotblk] = rBh[i];
            }
        }
    };

    auto compute = [&](int buf) {
        #pragma unroll
        for (int ks = 0; ks < 2; ks++) {
            int sb = ks * 8;
            uint32_t afr[WN][4], bfr[4][2];
            #pragma unroll
            for (int mt = 0; mt < WN; mt++) {
                int r0 = m0w + mt * 16 + g;
                int r1 = r0 + 8;
                afr[mt][0] = As32[buf][r0 * 16 + ((sb + tg) ^ swA(r0))];
                afr[mt][1] = As32[buf][r1 * 16 + ((sb + tg) ^ swA(r1))];
                afr[mt][2] = As32[buf][r0 * 16 + ((sb + tg + 4) ^ swA(r0))];
                afr[mt][3] = As32[buf][r1 * 16 + ((sb + tg + 4) ^ swA(r1))];
            }
            #pragma unroll
            for (int nt = 0; nt < 4; nt++) {
                int c0 = n0w + nt * 8 + g;
                int sw = (BLAY == 2) ? swA(c0) : swB(c0);
                bfr[nt][0] = Bs32[buf][c0 * 16 + ((sb + tg) ^ sw)];
                bfr[nt][1] = Bs32[buf][c0 * 16 + ((sb + tg + 4) ^ sw)];
            }
            #pragma unroll
            for (int mt = 0; mt < WN; mt++)
                #pragma unroll
                for (int nt = 0; nt < 4; nt++)
                    mma_f16(cacc[mt][nt], afr[mt], bfr[nt]);
        }
    };

    stage(0);
    commit(0);
    if (Keff > 32) stage(32);
    __syncthreads();
    int buf = 0;
    for (int kk = 0; kk < Keff; kk += 32) {
        if (kk + 32 < Keff) {
            commit(buf ^ 1);
            if (kk + 64 < Keff) stage(kk + 64);
        }
        compute(buf);
        __syncthreads();
        buf ^= 1;
    }

    float* Cf = (float*)Cv + offC;
    f16* Ch = (f16*)Cv + offC;
    #pragma unroll
    for (int mt = 0; mt < WN; mt++) {
        #pragma unroll
        for (int half_ = 0; half_ < 2; half_++) {
            int lr = bm + m0w + mt * 16 + g + half_ * 8;
            bool rowok = (MODE == 0) ? (lr < M) : (lr < cnt);
            if (!rowok) continue;
            size_t orow = (MODE == 0) ? (size_t)lr : (size_t)(base + lr);
            float scale = (MODE == 2) ? g_perm_w[base + lr] : 1.f;
            #pragma unroll
            for (int nt = 0; nt < 4; nt++) {
                int col = bn + n0w + nt * 8 + 2 * tg;
                if (col >= N) continue;
                float v0 = cacc[mt][nt][half_ * 2 + 0];
                float v1 = cacc[mt][nt][half_ * 2 + 1];
                if (MODE == 2) { v0 *= scale; v1 *= scale; }
                if (CBF) {
                    *(__half2*)(Ch + orow * ldc + col) = __floats2half2_rn(v0, v1);
                } else {
                    if (MODE == 0 && resid) {
                        float2 rv = *(const float2*)(resid + orow * ldc + col);
                        v0 += rv.x; v1 += rv.y;
                    }
                    *(float2*)(Cf + orow * ldc + col) = make_float2(v0, v1);
                }
            }
        }
    }
}

// ---------------- fused gated up-proj: C = silu(A@B1) * (A@B3), f16 out ----
// MODE 0: dense rows; MODE 1: rows gathered (expert z). B fp32 [K][N].
template<int MODE, int WN>
__global__ void __launch_bounds__(256)
gemm_dual(const f16* __restrict__ A, const float* __restrict__ B1g,
          const float* __restrict__ B3g, f16* __restrict__ C,
          int M, int N, int K, int lda, long long strB) {
    const int NCOLS = WN * 32;
    __shared__ uint32_t As32[2][2048];
    __shared__ uint32_t B1s32[2][WN * 512];
    __shared__ uint32_t B3s32[2][WN * 512];
    __shared__ int stoks[128];

    int tid = threadIdx.x;
    int warp = tid >> 5, lane = tid & 31;
    int g = lane >> 2, tg = lane & 3;
    int wm = warp / WN, wn = warp % WN;
    int m0w = wm * (WN * 16), n0w = wn * 32;

    int bn = blockIdx.x * NCOLS;
    int bm = blockIdx.y * 128;
    int z = blockIdx.z;

    int cnt = M, base = 0;
    if (MODE == 1) {
        cnt = g_counts[z];
        base = g_offsets[z];
        if (bm >= cnt) return;
        if (tid < 128) stoks[tid] = (bm + tid < cnt) ? g_perm_token[base + bm + tid] : 0;
        __syncthreads();
    }
    const float* B1 = B1g + (long long)z * strB;
    const float* B3 = B3g + (long long)z * strB;

    float acc1[WN][4][4], acc3[WN][4][4];
    #pragma unroll
    for (int a = 0; a < WN; a++)
        #pragma unroll
        for (int b = 0; b < 4; b++)
            #pragma unroll
            for (int c = 0; c < 4; c++) { acc1[a][b][c] = 0.f; acc3[a][b][c] = 0.f; }

    uint4 rA[2];
    float4 rB1[WN], rB3[WN];

    auto stage = [&](int kk) {
        #pragma unroll
        for (int i = 0; i < 2; i++) {
            int fidx = tid + i * 256;
            int r = fidx >> 2, c8 = fidx & 3;
            uint4 v = make_uint4(0, 0, 0, 0);
            if (MODE == 0) {
                if (bm + r < M) v = *(const uint4*)(A + (size_t)(bm + r) * lda + kk + c8 * 8);
            } else {
                if (bm + r < cnt) {
                    int tok = stoks[r];
                    v = *(const uint4*)(A + (size_t)tok * lda + kk + c8 * 8);
                }
            }
            rA[i] = v;
        }
        #pragma unroll
        for (int i = 0; i < WN; i++) {
            int fidx = tid + i * 256;
            int r = fidx / (NCOLS / 4), c4 = fidx % (NCOLS / 4);
            int col = bn + c4 * 4;
            float4 v1 = make_float4(0.f, 0.f, 0.f, 0.f);
            float4 v3 = v1;
            if (col < N) {
                v1 = *(const float4*)(B1 + (size_t)(kk + r) * N + col);
                v3 = *(const float4*)(B3 + (size_t)(kk + r) * N + col);
            }
            rB1[i] = v1; rB3[i] = v3;
        }
    };

    auto commit = [&](int buf) {
        #pragma unroll
        for (int i = 0; i < 2; i++) {
            int fidx = tid + i * 256;
            int r = fidx >> 2, c8 = fidx & 3;
            int slotblk = (c8 * 4) ^ swA(r);
            *(uint4*)&As32[buf][r * 16 + slotblk] = rA[i];
        }
        uint16_t* b1 = (uint16_t*)B1s32[buf];
        uint16_t* b3 = (uint16_t*)B3s32[buf];
        #pragma unroll
        for (int i = 0; i < WN; i++) {
            int fidx = tid + i * 256;
            int r = fidx / (NCOLS / 4), c4 = fidx % (NCOLS / 4);
            int sig = r >> 1, odd = r & 1;
            float w1[4] = {rB1[i].x, rB1[i].y, rB1[i].z, rB1[i].w};
            float w3[4] = {rB3[i].x, rB3[i].y, rB3[i].z, rB3[i].w};
            #pragma unroll
            for (int j = 0; j < 4; j++) {
                int col = c4 * 4 + j;
                int slot = (sig ^ swB(col)) * 2 + odd;
                f16 h1 = __float2half_rn(w1[j]);
                f16 h3 = __float2half_rn(w3[j]);
                b1[col * 32 + slot] = *(uint16_t*)&h1;
                b3[col * 32 + slot] = *(uint16_t*)&h3;
            }
        }
    };

    auto compute = [&](int buf) {
        #pragma unroll
        for (int ks = 0; ks < 2; ks++) {
            int sb = ks * 8;
            uint32_t afr[WN][4], b1fr[4][2], b3fr[4][2];
            #pragma unroll
            for (int mt = 0; mt < WN; mt++) {
                int r0 = m0w + mt * 16 + g;
                int r1 = r0 + 8;
                afr[mt][0] = As32[buf][r0 * 16 + ((sb + tg) ^ swA(r0))];
                afr[mt][1] = As32[buf][r1 * 16 + ((sb + tg) ^ swA(r1))];
                afr[mt][2] = As32[buf][r0 * 16 + ((sb + tg + 4) ^ swA(r0))];
                afr[mt][3] = As32[buf][r1 * 16 + ((sb + tg + 4) ^ swA(r1))];
            }
            #pragma unroll
            for (int nt = 0; nt < 4; nt++) {
                int c0 = n0w + nt * 8 + g;
                int sw = swB(c0);
                b1fr[nt][0] = B1s32[buf][c0 * 16 + ((sb + tg) ^ sw)];
                b1fr[nt][1] = B1s32[buf][c0 * 16 + ((sb + tg + 4) ^ sw)];
                b3fr[nt][0] = B3s32[buf][c0 * 16 + ((sb + tg) ^ sw)];
                b3fr[nt][1] = B3s32[buf][c0 * 16 + ((sb + tg + 4) ^ sw)];
            }
            #pragma unroll
            for (int mt = 0; mt < WN; mt++)
                #pragma unroll
                for (int nt = 0; nt < 4; nt++) {
                    mma_f16(acc1[mt][nt], afr[mt], b1fr[nt]);
                    mma_f16(acc3[mt][nt], afr[mt], b3fr[nt]);
                }
        }
    };

    stage(0);
    commit(0);
    if (K > 32) stage(32);
    __syncthreads();
    int buf = 0;
    for (int kk = 0; kk < K; kk += 32) {
        if (kk + 32 < K) {
            commit(buf ^ 1);
            if (kk + 64 < K) stage(kk + 64);
        }
        compute(buf);
        __syncthreads();
        buf ^= 1;
    }

    #pragma unroll
    for (int mt = 0; mt < WN; mt++) {
        #pragma unroll
        for (int half_ = 0; half_ < 2; half_++) {
            int lr = bm + m0w + mt * 16 + g + half_ * 8;
            bool rowok = (MODE == 0) ? (lr < M) : (lr < cnt);
            if (!rowok) continue;
            size_t orow = (MODE == 0) ? (size_t)lr : (size_t)(base + lr);
            #pragma unroll
            for (int nt = 0; nt < 4; nt++) {
                int col = bn + n0w + nt * 8 + 2 * tg;
                if (col >= N) continue;
                float a0 = acc1[mt][nt][half_ * 2 + 0];
                float a1 = acc1[mt][nt][half_ * 2 + 1];
                float b0 = acc3[mt][nt][half_ * 2 + 0];
                float b1 = acc3[mt][nt][half_ * 2 + 1];
                *(__half2*)(C + orow * N + col) =
                    __floats2half2_rn(silu_f(a0) * b0, silu_f(a1) * b1);
            }
        }
    }
}

// ---------------- pack per-head K ----------------
__global__ void prep_k_kernel(const f16* __restrict__ kvph, const float* __restrict__ kvF,
                              f16* __restrict__ kh) {
    long long i = (long long)blockIdx.x * 256 + threadIdx.x;
    if (i >= (long long)BH * SEQ * QK_HD) return;
    int d = (int)(i & 127);
    long long zs = i >> 7;
    int s = (int)(zs & (SEQ - 1));
    int zz = (int)(zs >> 10);
    int h = zz & 7, b = zz >> 3;
    size_t t = (size_t)b * SEQ + s;
    f16 val;
    if (d < NOPE) val = kvph[t * KVB_N + h * (NOPE + V_HD) + d];
    else          val = __float2half_rn(kvF[t * KVA_N + KV_LORA + (d - NOPE)]);
    kh[i] = val;
}

// ---------------- causal softmax (f16 in-place) ----------------
__global__ void softmax_kernel(f16* __restrict__ Ph) {
    int r = blockIdx.x;
    long long zoff = (long long)blockIdx.y * SEQ * SEQ + (long long)r * SEQ;
    f16* row = Ph + zoff;
    int n = r + 1;
    int tid = threadIdx.x;
    float v[4];
    float m = -1e30f;
    #pragma unroll
    for (int j = 0; j < 4; j++) {
        int c = tid + j * 256;
        v[j] = (c < n) ? __half2float(row[c]) : -1e30f;
        m = fmaxf(m, v[j]);
    }
    m = blockReduceMax256(m);
    float e[4], l = 0.f;
    #pragma unroll
    for (int j = 0; j < 4; j++) {
        int c = tid + j * 256;
        e[j] = (c < n) ? __expf(ATTN_SCALE * (v[j] - m)) : 0.f;
        l += e[j];
    }
    l = blockReduceSum256(l);
    float inv = 1.f / l;
    #pragma unroll
    for (int j = 0; j < 4; j++) {
        int c = tid + j * 256;
        row[c] = __float2half_rn(e[j] * inv);
    }
}

// ---------------- gate / routing ----------------
__global__ void zero_counts_kernel() {
    if (threadIdx.x < N_EXP) g_counts[threadIdx.x] = 0;
}

__global__ void gate_kernel(const float* __restrict__ xf, const float* __restrict__ gw,
                            const float* __restrict__ gb) {
    int t = blockIdx.x;
    __shared__ float sscore[N_EXP];
    int tid = threadIdx.x, warp = tid >> 5, lane = tid & 31;
    for (int e = warp; e < N_EXP; e += 4) {
        float s = 0.f;
        for (int d = lane; d < DIM; d += 32) s += xf[(size_t)t * DIM + d] * gw[(size_t)e * DIM + d];
        #pragma unroll
        for (int o = 16; o > 0; o >>= 1) s += __shfl_xor_sync(0xffffffffu, s, o);
        if (lane == 0) sscore[e] = 1.f / (1.f + expf(-s));
    }
    __syncthreads();
    if (tid == 0) {
        float orig[N_EXP], s[N_EXP];
        for (int e = 0; e < N_EXP; e++) { orig[e] = sscore[e]; s[e] = orig[e] + gb[e]; }
        float gs[N_GROUPS];
        for (int gg = 0; gg < N_GROUPS; gg++) {
            float m1 = -1e30f, m2 = -1e30f;
            for (int k = 0; k < 4; k++) {
                float v = s[gg * 4 + k];
                if (v > m1) { m2 = m1; m1 = v; } else if (v > m2) m2 = v;
            }
            gs[gg] = m1 + m2;
        }
        bool gsel[N_GROUPS] = {};
        for (int r = 0; r < TOPK_G; r++) {
            int best = -1; float bv = -1e30f;
            for (int gg = 0; gg < N_GROUPS; gg++)
                if (!gsel[gg] && gs[gg] > bv) { bv = gs[gg]; best = gg; }
            gsel[best] = true;
        }
        for (int gg = 0; gg < N_GROUPS; gg++)
            if (!gsel[gg]) for (int k = 0; k < 4; k++) s[gg * 4 + k] = -1e30f;
        int idx[TOPK]; bool used[N_EXP] = {};
        for (int r = 0; r < TOPK; r++) {
            int best = -1; float bv = -2e30f;
            for (int e = 0; e < N_EXP; e++)
                if (!used[e] && s[e] > bv) { bv = s[e]; best = e; }
            used[best] = true; idx[r] = best;
        }
        float wsum = 0.f;
        for (int r = 0; r < TOPK; r++) wsum += orig[idx[r]];
        float inv = 1.f / (wsum + 1e-20f);
        for (int r = 0; r < TOPK; r++) {
            g_expt_idx[t * TOPK + r] = idx[r];
            g_expt_w[t * TOPK + r] = orig[idx[r]] * inv;
            atomicAdd(&g_counts[idx[r]], 1);
        }
    }
}

__global__ void offsets_kernel() {
    if (threadIdx.x == 0) {
        int acc = 0;
        for (int e = 0; e < N_EXP; e++) {
            g_offsets[e] = acc;
            g_cursor[e] = acc;
            acc += g_counts[e];
        }
    }
}

__global__ void scatter_kernel() {
    int i = blockIdx.x * blockDim.x + threadIdx.x;
    if (i < NSLOT) {
        int e = g_expt_idx[i];
        int pos = atomicAdd(&g_cursor[e], 1);
        g_perm_token[pos] = i >> 2;
        g_perm_w[pos] = g_expt_w[i];
        g_slot_of[i] = pos;
    }
}

// ---------------- final combine (float4) ----------------
__global__ void final_kernel(float* __restrict__ out) {
    int t = blockIdx.x;
    int s0 = g_slot_of[t * 4 + 0], s1 = g_slot_of[t * 4 + 1];
    int s2 = g_slot_of[t * 4 + 2], s3 = g_slot_of[t * 4 + 3];
    int i = threadIdx.x;
    const float4* x2v = (const float4*)(g_x2 + (size_t)t * DIM);
    const float4* zbv = (const float4*)(g_zb + (size_t)t * DIM);
    const float4* y0 = (const float4*)(g_ybuf + (size_t)s0 * DIM);
    const float4* y1 = (const float4*)(g_ybuf + (size_t)s1 * DIM);
    const float4* y2 = (const float4*)(g_ybuf + (size_t)s2 * DIM);
    const float4* y3 = (const float4*)(g_ybuf + (size_t)s3 * DIM);
    float4 a = x2v[i], b = zbv[i], c0 = y0[i], c1 = y1[i], c2 = y2[i], c3 = y3[i];
    float4 r = make_float4(a.x + b.x + c0.x + c1.x + c2.x + c3.x,
                           a.y + b.y + c0.y + c1.y + c2.y + c3.y,
                           a.z + b.z + c0.z + c1.z + c2.z + c3.z,
                           a.w + b.w + c0.w + c1.w + c2.w + c3.w);
    *(float4*)(out + (size_t)t * DIM + i * 4) = r;
}

// ---------------- launcher ----------------
extern "C" void kernel_launch(void* const* d_in, const int* in_sizes, int n_in,
                              void* d_out, int out_size) {
    const float* x       = (const float*)d_in[0];
    const float* norm_a  = (const float*)d_in[1];
    const float* wq      = (const float*)d_in[2];
    const float* wkv_a   = (const float*)d_in[3];
    const float* kvnw    = (const float*)d_in[4];
    const float* wkv_b   = (const float*)d_in[5];
    const float* wo      = (const float*)d_in[6];
    const float* norm_m  = (const float*)d_in[7];
    const float* gate_w  = (const float*)d_in[8];
    const float* gate_b  = (const float*)d_in[9];
    const float* ew1     = (const float*)d_in[10];
    const float* ew2     = (const float*)d_in[11];
    const float* ew3     = (const float*)d_in[12];
    const float* sw1     = (const float*)d_in[13];
    const float* sw2     = (const float*)d_in[14];
    const float* sw3     = (const float*)d_in[15];
    float* out = (float*)d_out;

    float *kvF, *x2, *xf, *ybuf, *zb;
    f16 *x1h, *qh, *cnh, *kvph, *khh, *Ph, *attnh, *xfh, *hbufh, *hsh;
    cudaGetSymbolAddress((void**)&kvF, g_kvF);
    cudaGetSymbolAddress((void**)&x2,  g_x2);
    cudaGetSymbolAddress((void**)&xf,  g_xf);
    cudaGetSymbolAddress((void**)&ybuf,g_ybuf);
    cudaGetSymbolAddress((void**)&zb,  g_zb);
    cudaGetSymbolAddress((void**)&x1h, g_x1h);
    cudaGetSymbolAddress((void**)&qh,  g_qh);
    cudaGetSymbolAddress((void**)&cnh, g_cnh);
    cudaGetSymbolAddress((void**)&kvph,g_kvph);
    cudaGetSymbolAddress((void**)&khh, g_khh);
    cudaGetSymbolAddress((void**)&Ph,  g_Ph);
    cudaGetSymbolAddress((void**)&attnh, g_attnh);
    cudaGetSymbolAddress((void**)&xfh, g_xfh);
    cudaGetSymbolAddress((void**)&hbufh, g_hbufh);
    cudaGetSymbolAddress((void**)&hsh, g_hsh);

    static cudaStream_t s1 = nullptr;
    static cudaEvent_t evF1, evJ1, evF2, evJ2;
    if (!s1) {
        cudaStreamCreateWithFlags(&s1, cudaStreamNonBlocking);
        cudaEventCreateWithFlags(&evF1, cudaEventDisableTiming);
        cudaEventCreateWithFlags(&evJ1, cudaEventDisableTiming);
        cudaEventCreateWithFlags(&evF2, cudaEventDisableTiming);
        cudaEventCreateWithFlags(&evJ2, cudaEventDisableTiming);
    }

    // 1) attention input norm -> fp16
    rmsnorm_kernel<<<TTOK, 256>>>(x, norm_a, nullptr, x1h, DIM, DIM);

    // ---- fork 1: q-proj on s1, kv chain on main ----
    cudaEventRecord(evF1, 0);
    cudaStreamWaitEvent(s1, evF1, 0);
    gemm_k<0,0,true,0,2><<<dim3(16,16,1), 256, 0, s1>>>(x1h, wq, qh, nullptr,
        TTOK, DIM, DIM, DIM, DIM, DIM, 1, 0,0,0,0,0,0);
    gemm_k<0,0,false,0,2><<<dim3(5,16,1), 256>>>(x1h, wkv_a, kvF, nullptr,
        TTOK, KVA_N, DIM, DIM, KVA_N, KVA_N, 1, 0,0,0,0,0,0);
    rmsnorm_kernel<<<TTOK, 256>>>(kvF, kvnw, nullptr, cnh, KV_LORA, KVA_N);
    gemm_k<0,0,true,0,2><<<dim3(24,16,1), 256>>>(cnh, wkv_b, kvph, nullptr,
        TTOK, KVB_N, KV_LORA, KV_LORA, KVB_N, KVB_N, 1, 0,0,0,0,0,0);
    prep_k_kernel<<<(int)(((long long)BH*SEQ*QK_HD + 255)/256), 256>>>(kvph, kvF, khh);
    cudaEventRecord(evJ1, s1);
    cudaStreamWaitEvent(0, evJ1, 0);

    // 7) scores = q @ kh^T, triangular 128x64 tiles, f16 out into Ph
    gemm_k<0,2,true,1,2><<<dim3(72,1,BH), 256>>>(qh, khh, Ph, nullptr,
        SEQ, SEQ, QK_HD, DIM, QK_HD, SEQ, HEADS,
        (long long)SEQ*DIM, 128,
        (long long)HEADS*SEQ*QK_HD, (long long)SEQ*QK_HD,
        (long long)HEADS*SEQ*SEQ, (long long)SEQ*SEQ);
    // 8) causal softmax in-place on Ph
    softmax_kernel<<<dim3(SEQ, BH), 256>>>(Ph);
    // 9) attn = P @ V
    gemm_k<0,1,true,2,2><<<dim3(2,8,BH), 256>>>(Ph, kvph + NOPE, attnh, nullptr,
        SEQ, V_HD, SEQ, SEQ, KVB_N, DIM, HEADS,
        (long long)HEADS*SEQ*SEQ, (long long)SEQ*SEQ,
        (long long)SEQ*KVB_N, (long long)(NOPE+V_HD),
        (long long)SEQ*DIM, 128);
    // 10) x2 = x + attn @ wo
    gemm_k<0,0,false,0,2><<<dim3(16,16,1), 256>>>(attnh, wo, x2, x,
        TTOK, DIM, DIM, DIM, DIM, DIM, 1, 0,0,0,0,0,0);
    // 11) moe input norm
    rmsnorm_kernel<<<TTOK, 256>>>(x2, norm_m, xf, xfh, DIM, DIM);

    // ---- fork 2: shared expert on s1, routing + routed experts on main ----
    cudaEventRecord(evF2, 0);
    cudaStreamWaitEvent(s1, evF2, 0);
    gemm_dual<0,2><<<dim3(8,16,1), 256, 0, s1>>>(xfh, sw1, sw3, hsh,
        TTOK, INTER, DIM, DIM, 0);
    gemm_k<0,0,false,0,2><<<dim3(16,16,1), 256, 0, s1>>>(hsh, sw2, zb, nullptr,
        TTOK, DIM, INTER, INTER, DIM, DIM, 1, 0,0,0,0,0,0);
    cudaEventRecord(evJ2, s1);

    // 12) gate + routing (main)
    zero_counts_kernel<<<1, 32>>>();
    gate_kernel<<<TTOK, 128>>>(xf, gate_w, gate_b);
    offsets_kernel<<<1, 32>>>();
    scatter_kernel<<<NSLOT/256, 256>>>();
    // 13) routed experts (fp32 weights, in-kernel f16 convert)
    gemm_dual<1,2><<<dim3(8,16,N_EXP), 256>>>(xfh, ew1, ew3, hbufh,
        0, INTER, DIM, DIM, (long long)DIM*INTER);
    gemm_k<2,0,false,0,2><<<dim3(16,16,N_EXP), 256>>>(hbufh, ew2, ybuf, nullptr,
        0, DIM, INTER, INTER, DIM, DIM, 1, 0,0, (long long)INTER*DIM,0, 0,0);
    // join shared expert before final
    cudaStreamWaitEvent(0, evJ2, 0);

    // 15) final combine
    final_kernel<<<TTOK, 256>>>(out);
}

// round 14
// speedup vs baseline: 1.0932x; 1.0439x over previous
#include <cuda_runtime.h>
#include <cuda_fp16.h>
#include <math.h>
#include <stdint.h>

// ---------------- problem constants ----------------
#define TTOK   2048
#define BATCH  2
#define SEQ    1024
#define DIM    1024
#define HEADS  8
#define BH     16
#define QK_HD  128
#define V_HD   128
#define NOPE   64
#define ROPE   64
#define KV_LORA 256
#define KVA_N  320
#define KVB_N  1536
#define N_EXP  32
#define N_GROUPS 8
#define TOPK   4
#define TOPK_G 4
#define INTER  512
#define NSLOT  8192
#define EPS    1e-6f
#define ATTN_SCALE 0.08838834764831843f

typedef __half f16;

// ---------------- scratch ----------------
__device__ float g_kvF [TTOK * KVA_N];
__device__ float g_x2  [TTOK * DIM];
__device__ float g_xf  [TTOK * DIM];
__device__ float g_ybuf[NSLOT * DIM];
__device__ float g_zb  [TTOK * DIM];

__device__ f16 g_x1h [TTOK * DIM];
__device__ f16 g_qh  [TTOK * DIM];
__device__ f16 g_cnh [TTOK * KV_LORA];
__device__ f16 g_kvph[TTOK * KVB_N];
__device__ f16 g_khh [(size_t)BH * SEQ * QK_HD];
__device__ f16 g_Ph  [(size_t)BH * SEQ * SEQ];   // f16 scores -> softmaxed in place
__device__ f16 g_attnh[TTOK * DIM];
__device__ f16 g_xfh [TTOK * DIM];
__device__ f16 g_hbufh[NSLOT * INTER];
__device__ f16 g_hsh [TTOK * INTER];

__device__ int   g_counts [N_EXP];
__device__ int   g_offsets[N_EXP];
__device__ int   g_cursor [N_EXP];
__device__ int   g_expt_idx[NSLOT];
__device__ float g_expt_w [NSLOT];
__device__ int   g_perm_token[NSLOT];
__device__ float g_perm_w   [NSLOT];
__device__ int   g_slot_of  [NSLOT];

// ---------------- helpers ----------------
__device__ __forceinline__ float blockReduceSum256(float v) {
    __shared__ float red[8];
    int lane = threadIdx.x & 31, warp = threadIdx.x >> 5;
    #pragma unroll
    for (int o = 16; o > 0; o >>= 1) v += __shfl_xor_sync(0xffffffffu, v, o);
    if (lane == 0) red[warp] = v;
    __syncthreads();
    if (warp == 0) {
        v = (lane < 8) ? red[lane] : 0.f;
        #pragma unroll
        for (int o = 4; o > 0; o >>= 1) v += __shfl_xor_sync(0xffffffffu, v, o);
        if (lane == 0) red[0] = v;
    }
    __syncthreads();
    return red[0];
}

__device__ __forceinline__ float blockReduceMax256(float v) {
    __shared__ float red[8];
    int lane = threadIdx.x & 31, warp = threadIdx.x >> 5;
    #pragma unroll
    for (int o = 16; o > 0; o >>= 1) v = fmaxf(v, __shfl_xor_sync(0xffffffffu, v, o));
    if (lane == 0) red[warp] = v;
    __syncthreads();
    if (warp == 0) {
        v = (lane < 8) ? red[lane] : -1e30f;
        #pragma unroll
        for (int o = 4; o > 0; o >>= 1) v = fmaxf(v, __shfl_xor_sync(0xffffffffu, v, o));
        if (lane == 0) red[0] = v;
    }
    __syncthreads();
    return red[0];
}

__device__ __forceinline__ void mma_f16(float* c, const uint32_t* a, const uint32_t* b) {
    asm volatile(
        "mma.sync.aligned.m16n8k16.row.col.f32.f16.f16.f32 "
        "{%0,%1,%2,%3}, {%4,%5,%6,%7}, {%8,%9}, {%0,%1,%2,%3};\n"
        : "+f"(c[0]), "+f"(c[1]), "+f"(c[2]), "+f"(c[3])
        : "r"(a[0]), "r"(a[1]), "r"(a[2]), "r"(a[3]), "r"(b[0]), "r"(b[1]));
}

__device__ __forceinline__ int swA(int row) { return ((row >> 1) & 3) << 2; }
__device__ __forceinline__ int swB(int col) { return (((col >> 1) & 3) << 2) ^ ((col >> 2) & 3); }

__device__ __forceinline__ float silu_f(float a) { return a / (1.f + __expf(-a)); }

// ---------------- rmsnorm (float4 vectorized) ----------------
__global__ void rmsnorm_kernel(const float* __restrict__ x, const float* __restrict__ w,
                               float* __restrict__ o32, f16* __restrict__ o16,
                               int D, int in_stride) {
    int t = blockIdx.x;
    const float4* row = (const float4*)(x + (size_t)t * in_stride);
    const float4* wv4 = (const float4*)w;
    int nv = D >> 2;
    float ss = 0.f;
    for (int i = threadIdx.x; i < nv; i += 256) {
        float4 v = row[i];
        ss += v.x * v.x + v.y * v.y + v.z * v.z + v.w * v.w;
    }
    ss = blockReduceSum256(ss);
    __shared__ float inv;
    if (threadIdx.x == 0) inv = rsqrtf(ss / (float)D + EPS);
    __syncthreads();
    float iv = inv;
    for (int i = threadIdx.x; i < nv; i += 256) {
        float4 v = row[i];
        float4 wv = wv4[i];
        float4 r = make_float4(v.x * iv * wv.x, v.y * iv * wv.y,
                               v.z * iv * wv.z, v.w * iv * wv.w);
        if (o32) *(float4*)(o32 + (size_t)t * D + i * 4) = r;
        if (o16) {
            __half2* oh = (__half2*)(o16 + (size_t)t * D + i * 4);
            oh[0] = __floats2half2_rn(r.x, r.y);
            oh[1] = __floats2half2_rn(r.z, r.w);
        }
    }
}

// ---------------- fp16 tensor-core GEMM -----------------------------------
// CTA tile: 128 x (WN*32). MODE 0: dense; MODE 1: A gathered; MODE 2: expert
// offset + perm_w scale. BLAY: 0 = B fp32 [K][N]; 1 = B f16 [K][N]; 2 = B f16 [N][K].
// CBF: C f16. CAUSAL: 0 none; 1 triangular decode; 2 K clip at bm+128.
// zbase: expert/batch z offset (for split launches).
template<int MODE, int BLAY, bool CBF, int CAUSAL, int WN>
__global__ void __launch_bounds__(256)
gemm_k(const f16* __restrict__ A, const void* __restrict__ Bv, void* __restrict__ Cv,
       const float* __restrict__ resid,
       int M, int N, int K, int lda, int ldb, int ldc, int zdiv,
       long long sA1, long long sA2, long long sB1, long long sB2,
       long long sC1, long long sC2, int zbase) {
    const int NCOLS = WN * 32;
    __shared__ uint32_t As32[2][2048];
    __shared__ uint32_t Bs32[2][WN * 512];
    __shared__ int stoks[128];

    int tid = threadIdx.x;
    int warp = tid >> 5, lane = tid & 31;
    int g = lane >> 2, tg = lane & 3;
    int wm = warp / WN, wn = warp % WN;
    int m0w = wm * (WN * 16), n0w = wn * 32;

    int bn, bm;
    if (CAUSAL == 1) {
        const int R = 128 / NCOLS;
        int ti = blockIdx.x;
        int bmt = 0;
        while (R * (bmt + 1) * (bmt + 2) / 2 <= ti) bmt++;
        int bnt = ti - R * bmt * (bmt + 1) / 2;
        bm = bmt * 128; bn = bnt * NCOLS;
    } else {
        bn = blockIdx.x * NCOLS;
        bm = blockIdx.y * 128;
    }
    int z = blockIdx.z + zbase;
    long long offA = (long long)(z / zdiv) * sA1 + (long long)(z % zdiv) * sA2;
    long long offB = (long long)(z / zdiv) * sB1 + (long long)(z % zdiv) * sB2;
    long long offC = (long long)(z / zdiv) * sC1 + (long long)(z % zdiv) * sC2;

    int cnt = M, base = 0;
    if (MODE != 0) {
        cnt = g_counts[z];
        base = g_offsets[z];
        if (bm >= cnt) return;
    }
    if (MODE == 1) {
        if (tid < 128) stoks[tid] = (bm + tid < cnt) ? g_perm_token[base + bm + tid] : 0;
        __syncthreads();
    }

    const f16* Ap = A + offA;
    const float* Bf = (BLAY == 0) ? ((const float*)Bv + offB) : nullptr;
    const f16*  Bh = (BLAY != 0) ? ((const f16*)Bv + offB) : nullptr;

    int Keff = K;
    if (CAUSAL == 2) { int kl = bm + 128; Keff = kl < K ? kl : K; }

    float cacc[WN][4][4];
    #pragma unroll
    for (int a = 0; a < WN; a++)
        #pragma unroll
        for (int b = 0; b < 4; b++)
            #pragma unroll
            for (int c = 0; c < 4; c++) cacc[a][b][c] = 0.f;

    uint4 rA[2];
    float4 rBf[WN];
    uint4 rBh[WN / 2];

    auto stage = [&](int kk) {
        #pragma unroll
        for (int i = 0; i < 2; i++) {
            int fidx = tid + i * 256;
            int r = fidx >> 2, c8 = fidx & 3;
            uint4 v = make_uint4(0, 0, 0, 0);
            if (MODE == 0) {
                int row = bm + r;
                if (row < M) v = *(const uint4*)(Ap + (size_t)row * lda + kk + c8 * 8);
            } else if (MODE == 1) {
                if (bm + r < cnt) {
                    int tok = stoks[r];
                    v = *(const uint4*)(Ap + (size_t)tok * lda + kk + c8 * 8);
                }
            } else {
                if (bm + r < cnt)
                    v = *(const uint4*)(Ap + (size_t)(base + bm + r) * lda + kk + c8 * 8);
            }
            rA[i] = v;
        }
        if (BLAY == 0) {
            #pragma unroll
            for (int i = 0; i < WN; i++) {
                int fidx = tid + i * 256;
                int r = fidx / (NCOLS / 4), c4 = fidx % (NCOLS / 4);
                int col = bn + c4 * 4;
                float4 v = make_float4(0.f, 0.f, 0.f, 0.f);
                if (col < N) v = *(const float4*)(Bf + (size_t)(kk + r) * ldb + col);
                rBf[i] = v;
            }
        } else if (BLAY == 1) {
            #pragma unroll
            for (int i = 0; i < WN / 2; i++) {
                int fidx = tid + i * 256;
                int r = fidx / (NCOLS / 8), c8 = fidx % (NCOLS / 8);
                int col = bn + c8 * 8;
                uint4 v = make_uint4(0, 0, 0, 0);
                if (col < N) v = *(const uint4*)(Bh + (size_t)(kk + r) * ldb + col);
                rBh[i] = v;
            }
        } else {
            #pragma unroll
            for (int i = 0; i < WN / 2; i++) {
                int fidx = tid + i * 256;
                int r = fidx >> 2, c8 = fidx & 3;
                uint4 v = make_uint4(0, 0, 0, 0);
                if (bn + r < N) v = *(const uint4*)(Bh + (size_t)(bn + r) * ldb + kk + c8 * 8);
                rBh[i] = v;
            }
        }
    };

    auto commit = [&](int buf) {
        #pragma unroll
        for (int i = 0; i < 2; i++) {
            int fidx = tid + i * 256;
            int r = fidx >> 2, c8 = fidx & 3;
            int slotblk = (c8 * 4) ^ swA(r);
            *(uint4*)&As32[buf][r * 16 + slotblk] = rA[i];
        }
        if (BLAY == 0) {
            uint16_t* Bs16 = (uint16_t*)Bs32[buf];
            #pragma unroll
            for (int i = 0; i < WN; i++) {
                int fidx = tid + i * 256;
                int r = fidx / (NCOLS / 4), c4 = fidx % (NCOLS / 4);
                int sig = r >> 1, odd = r & 1;
                float vv[4] = {rBf[i].x, rBf[i].y, rBf[i].z, rBf[i].w};
                #pragma unroll
                for (int j = 0; j < 4; j++) {
                    int col = c4 * 4 + j;
                    f16 hv = __float2half_rn(vv[j]);
                    Bs16[col * 32 + (sig ^ swB(col)) * 2 + odd] = *(uint16_t*)&hv;
                }
            }
        } else if (BLAY == 1) {
            uint16_t* Bs16 = (uint16_t*)Bs32[buf];
            #pragma unroll
            for (int i = 0; i < WN / 2; i++) {
                int fidx = tid + i * 256;
                int r = fidx / (NCOLS / 8), c8 = fidx % (NCOLS / 8);
                int sig = r >> 1, odd = r & 1;
                const uint16_t* src = (const uint16_t*)&rBh[i];
                #pragma unroll
                for (int j = 0; j < 8; j++) {
                    int col = c8 * 8 + j;
                    Bs16[col * 32 + (sig ^ swB(col)) * 2 + odd] = src[j];
                }
            }
        } else {
            #pragma unroll
            for (int i = 0; i < WN / 2; i++) {
                int fidx = tid + i * 256;
                int r = fidx >> 2, c8 = fidx & 3;
                int slotblk = (c8 * 4) ^ swA(r);
                *(uint4*)&Bs32[buf][r * 16 + slotblk] = rBh[i];
            }
        }
    };

    auto compute = [&](int buf) {
        #pragma unroll
        for (int ks = 0; ks < 2; ks++) {
            int sb = ks * 8;
            uint32_t afr[WN][4], bfr[4][2];
            #pragma unroll
            for (int mt = 0; mt < WN; mt++) {
                int r0 = m0w + mt * 16 + g;
                int r1 = r0 + 8;
                afr[mt][0] = As32[buf][r0 * 16 + ((sb + tg) ^ swA(r0))];
                afr[mt][1] = As32[buf][r1 * 16 + ((sb + tg) ^ swA(r1))];
                afr[mt][2] = As32[buf][r0 * 16 + ((sb + tg + 4) ^ swA(r0))];
                afr[mt][3] = As32[buf][r1 * 16 + ((sb + tg + 4) ^ swA(r1))];
            }
            #pragma unroll
            for (int nt = 0; nt < 4; nt++) {
                int c0 = n0w + nt * 8 + g;
                int sw = (BLAY == 2) ? swA(c0) : swB(c0);
                bfr[nt][0] = Bs32[buf][c0 * 16 + ((sb + tg) ^ sw)];
                bfr[nt][1] = Bs32[buf][c0 * 16 + ((sb + tg + 4) ^ sw)];
            }
            #pragma unroll
            for (int mt = 0; mt < WN; mt++)
                #pragma unroll
                for (int nt = 0; nt < 4; nt++)
                    mma_f16(cacc[mt][nt], afr[mt], bfr[nt]);
        }
    };

    stage(0);
    commit(0);
    if (Keff > 32) stage(32);
    __syncthreads();
    int buf = 0;
    for (int kk = 0; kk < Keff; kk += 32) {
        if (kk + 32 < Keff) {
            commit(buf ^ 1);
            if (kk + 64 < Keff) stage(kk + 64);
        }
        compute(buf);
        __syncthreads();
        buf ^= 1;
    }

    float* Cf = (float*)Cv + offC;
    f16* Ch = (f16*)Cv + offC;
    #pragma unroll
    for (int mt = 0; mt < WN; mt++) {
        #pragma unroll
        for (int half_ = 0; half_ < 2; half_++) {
            int lr = bm + m0w + mt * 16 + g + half_ * 8;
            bool rowok = (MODE == 0) ? (lr < M) : (lr < cnt);
            if (!rowok) continue;
            size_t orow = (MODE == 0) ? (size_t)lr : (size_t)(base + lr);
            float scale = (MODE == 2) ? g_perm_w[base + lr] : 1.f;
            #pragma unroll
            for (int nt = 0; nt < 4; nt++) {
                int col = bn + n0w + nt * 8 + 2 * tg;
                if (col >= N) continue;
                float v0 = cacc[mt][nt][half_ * 2 + 0];
                float v1 = cacc[mt][nt][half_ * 2 + 1];
                if (MODE == 2) { v0 *= scale; v1 *= scale; }
                if (CBF) {
                    *(__half2*)(Ch + orow * ldc + col) = __floats2half2_rn(v0, v1);
                } else {
                    if (MODE == 0 && resid) {
                        float2 rv = *(const float2*)(resid + orow * ldc + col);
                        v0 += rv.x; v1 += rv.y;
                    }
                    *(float2*)(Cf + orow * ldc + col) = make_float2(v0, v1);
                }
            }
        }
    }
}

// ---------------- fused gated up-proj: C = silu(A@B1) * (A@B3), f16 out ----
// MODE 0: dense rows; MODE 1: rows gathered (expert z). B fp32 [K][N].
template<int MODE, int WN>
__global__ void __launch_bounds__(256)
gemm_dual(const f16* __restrict__ A, const float* __restrict__ B1g,
          const float* __restrict__ B3g, f16* __restrict__ C,
          int M, int N, int K, int lda, long long strB, int zbase) {
    const int NCOLS = WN * 32;
    __shared__ uint32_t As32[2][2048];
    __shared__ uint32_t B1s32[2][WN * 512];
    __shared__ uint32_t B3s32[2][WN * 512];
    __shared__ int stoks[128];

    int tid = threadIdx.x;
    int warp = tid >> 5, lane = tid & 31;
    int g = lane >> 2, tg = lane & 3;
    int wm = warp / WN, wn = warp % WN;
    int m0w = wm * (WN * 16), n0w = wn * 32;

    int bn = blockIdx.x * NCOLS;
    int bm = blockIdx.y * 128;
    int z = blockIdx.z + zbase;

    int cnt = M, base = 0;
    if (MODE == 1) {
        cnt = g_counts[z];
        base = g_offsets[z];
        if (bm >= cnt) return;
        if (tid < 128) stoks[tid] = (bm + tid < cnt) ? g_perm_token[base + bm + tid] : 0;
        __syncthreads();
    }
    const float* B1 = B1g + (long long)z * strB;
    const float* B3 = B3g + (long long)z * strB;

    float acc1[WN][4][4], acc3[WN][4][4];
    #pragma unroll
    for (int a = 0; a < WN; a++)
        #pragma unroll
        for (int b = 0; b < 4; b++)
            #pragma unroll
            for (int c = 0; c < 4; c++) { acc1[a][b][c] = 0.f; acc3[a][b][c] = 0.f; }

    uint4 rA[2];
    float4 rB1[WN], rB3[WN];

    auto stage = [&](int kk) {
        #pragma unroll
        for (int i = 0; i < 2; i++) {
            int fidx = tid + i * 256;
            int r = fidx >> 2, c8 = fidx & 3;
            uint4 v = make_uint4(0, 0, 0, 0);
            if (MODE == 0) {
                if (bm + r < M) v = *(const uint4*)(A + (size_t)(bm + r) * lda + kk + c8 * 8);
            } else {
                if (bm + r < cnt) {
                    int tok = stoks[r];
                    v = *(const uint4*)(A + (size_t)tok * lda + kk + c8 * 8);
                }
            }
            rA[i] = v;
        }
        #pragma unroll
        for (int i = 0; i < WN; i++) {
            int fidx = tid + i * 256;
            int r = fidx / (NCOLS / 4), c4 = fidx % (NCOLS / 4);
            int col = bn + c4 * 4;
            float4 v1 = make_float4(0.f, 0.f, 0.f, 0.f);
            float4 v3 = v1;
            if (col < N) {
                v1 = *(const float4*)(B1 + (size_t)(kk + r) * N + col);
                v3 = *(const float4*)(B3 + (size_t)(kk + r) * N + col);
            }
            rB1[i] = v1; rB3[i] = v3;
        }
    };

    auto commit = [&](int buf) {
        #pragma unroll
        for (int i = 0; i < 2; i++) {
            int fidx = tid + i * 256;
            int r = fidx >> 2, c8 = fidx & 3;
            int slotblk = (c8 * 4) ^ swA(r);
            *(uint4*)&As32[buf][r * 16 + slotblk] = rA[i];
        }
        uint16_t* b1 = (uint16_t*)B1s32[buf];
        uint16_t* b3 = (uint16_t*)B3s32[buf];
        #pragma unroll
        for (int i = 0; i < WN; i++) {
            int fidx = tid + i * 256;
            int r = fidx / (NCOLS / 4), c4 = fidx % (NCOLS / 4);
            int sig = r >> 1, odd = r & 1;
            float w1[4] = {rB1[i].x, rB1[i].y, rB1[i].z, rB1[i].w};
            float w3[4] = {rB3[i].x, rB3[i].y, rB3[i].z, rB3[i].w};
            #pragma unroll
            for (int j = 0; j < 4; j++) {
                int col = c4 * 4 + j;
                int slot = (sig ^ swB(col)) * 2 + odd;
                f16 h1 = __float2half_rn(w1[j]);
                f16 h3 = __float2half_rn(w3[j]);
                b1[col * 32 + slot] = *(uint16_t*)&h1;
                b3[col * 32 + slot] = *(uint16_t*)&h3;
            }
        }
    };

    auto compute = [&](int buf) {
        #pragma unroll
        for (int ks = 0; ks < 2; ks++) {
            int sb = ks * 8;
            uint32_t afr[WN][4], b1fr[4][2], b3fr[4][2];
            #pragma unroll
            for (int mt = 0; mt < WN; mt++) {
                int r0 = m0w + mt * 16 + g;
                int r1 = r0 + 8;
                afr[mt][0] = As32[buf][r0 * 16 + ((sb + tg) ^ swA(r0))];
                afr[mt][1] = As32[buf][r1 * 16 + ((sb + tg) ^ swA(r1))];
                afr[mt][2] = As32[buf][r0 * 16 + ((sb + tg + 4) ^ swA(r0))];
                afr[mt][3] = As32[buf][r1 * 16 + ((sb + tg + 4) ^ swA(r1))];
            }
            #pragma unroll
            for (int nt = 0; nt < 4; nt++) {
                int c0 = n0w + nt * 8 + g;
                int sw = swB(c0);
                b1fr[nt][0] = B1s32[buf][c0 * 16 + ((sb + tg) ^ sw)];
                b1fr[nt][1] = B1s32[buf][c0 * 16 + ((sb + tg + 4) ^ sw)];
                b3fr[nt][0] = B3s32[buf][c0 * 16 + ((sb + tg) ^ sw)];
                b3fr[nt][1] = B3s32[buf][c0 * 16 + ((sb + tg + 4) ^ sw)];
            }
            #pragma unroll
            for (int mt = 0; mt < WN; mt++)
                #pragma unroll
                for (int nt = 0; nt < 4; nt++) {
                    mma_f16(acc1[mt][nt], afr[mt], b1fr[nt]);
                    mma_f16(acc3[mt][nt], afr[mt], b3fr[nt]);
                }
        }
    };

    stage(0);
    commit(0);
    if (K > 32) stage(32);
    __syncthreads();
    int buf = 0;
    for (int kk = 0; kk < K; kk += 32) {
        if (kk + 32 < K) {
            commit(buf ^ 1);
            if (kk + 64 < K) stage(kk + 64);
        }
        compute(buf);
        __syncthreads();
        buf ^= 1;
    }

    #pragma unroll
    for (int mt = 0; mt < WN; mt++) {
        #pragma unroll
        for (int half_ = 0; half_ < 2; half_++) {
            int lr = bm + m0w + mt * 16 + g + half_ * 8;
            bool rowok = (MODE == 0) ? (lr < M) : (lr < cnt);
            if (!rowok) continue;
            size_t orow = (MODE == 0) ? (size_t)lr : (size_t)(base + lr);
            #pragma unroll
            for (int nt = 0; nt < 4; nt++) {
                int col = bn + n0w + nt * 8 + 2 * tg;
                if (col >= N) continue;
                float a0 = acc1[mt][nt][half_ * 2 + 0];
                float a1 = acc1[mt][nt][half_ * 2 + 1];
                float b0 = acc3[mt][nt][half_ * 2 + 0];
                float b1 = acc3[mt][nt][half_ * 2 + 1];
                *(__half2*)(C + orow * N + col) =
                    __floats2half2_rn(silu_f(a0) * b0, silu_f(a1) * b1);
            }
        }
    }
}

// ---------------- pack per-head K ----------------
__global__ void prep_k_kernel(const f16* __restrict__ kvph, const float* __restrict__ kvF,
                              f16* __restrict__ kh) {
    long long i = (long long)blockIdx.x * 256 + threadIdx.x;
    if (i >= (long long)BH * SEQ * QK_HD) return;
    int d = (int)(i & 127);
    long long zs = i >> 7;
    int s = (int)(zs & (SEQ - 1));
    int zz = (int)(zs >> 10);
    int h = zz & 7, b = zz >> 3;
    size_t t = (size_t)b * SEQ + s;
    f16 val;
    if (d < NOPE) val = kvph[t * KVB_N + h * (NOPE + V_HD) + d];
    else          val = __float2half_rn(kvF[t * KVA_N + KV_LORA + (d - NOPE)]);
    kh[i] = val;
}

// ---------------- causal softmax (f16 in-place) ----------------
__global__ void softmax_kernel(f16* __restrict__ Ph) {
    int r = blockIdx.x;
    long long zoff = (long long)blockIdx.y * SEQ * SEQ + (long long)r * SEQ;
    f16* row = Ph + zoff;
    int n = r + 1;
    int tid = threadIdx.x;
    float v[4];
    float m = -1e30f;
    #pragma unroll
    for (int j = 0; j < 4; j++) {
        int c = tid + j * 256;
        v[j] = (c < n) ? __half2float(row[c]) : -1e30f;
        m = fmaxf(m, v[j]);
    }
    m = blockReduceMax256(m);
    float e[4], l = 0.f;
    #pragma unroll
    for (int j = 0; j < 4; j++) {
        int c = tid + j * 256;
        e[j] = (c < n) ? __expf(ATTN_SCALE * (v[j] - m)) : 0.f;
        l += e[j];
    }
    l = blockReduceSum256(l);
    float inv = 1.f / l;
    #pragma unroll
    for (int j = 0; j < 4; j++) {
        int c = tid + j * 256;
        row[c] = __float2half_rn(e[j] * inv);
    }
}

// ---------------- gate / routing ----------------
__global__ void zero_counts_kernel() {
    if (threadIdx.x < N_EXP) g_counts[threadIdx.x] = 0;
}

__global__ void gate_kernel(const float* __restrict__ xf, const float* __restrict__ gw,
                            const float* __restrict__ gb) {
    int t = blockIdx.x;
    __shared__ float sscore[N_EXP];
    int tid = threadIdx.x, warp = tid >> 5, lane = tid & 31;
    for (int e = warp; e < N_EXP; e += 4) {
        float s = 0.f;
        for (int d = lane; d < DIM; d += 32) s += xf[(size_t)t * DIM + d] * gw[(size_t)e * DIM + d];
        #pragma unroll
        for (int o = 16; o > 0; o >>= 1) s += __shfl_xor_sync(0xffffffffu, s, o);
        if (lane == 0) sscore[e] = 1.f / (1.f + expf(-s));
    }
    __syncthreads();
    if (tid == 0) {
        float orig[N_EXP], s[N_EXP];
        for (int e = 0; e < N_EXP; e++) { orig[e] = sscore[e]; s[e] = orig[e] + gb[e]; }
        float gs[N_GROUPS];
        for (int gg = 0; gg < N_GROUPS; gg++) {
            float m1 = -1e30f, m2 = -1e30f;
            for (int k = 0; k < 4; k++) {
                float v = s[gg * 4 + k];
                if (v > m1) { m2 = m1; m1 = v; } else if (v > m2) m2 = v;
            }
            gs[gg] = m1 + m2;
        }
        bool gsel[N_GROUPS] = {};
        for (int r = 0; r < TOPK_G; r++) {
            int best = -1; float bv = -1e30f;
            for (int gg = 0; gg < N_GROUPS; gg++)
                if (!gsel[gg] && gs[gg] > bv) { bv = gs[gg]; best = gg; }
            gsel[best] = true;
        }
        for (int gg = 0; gg < N_GROUPS; gg++)
            if (!gsel[gg]) for (int k = 0; k < 4; k++) s[gg * 4 + k] = -1e30f;
        int idx[TOPK]; bool used[N_EXP] = {};
        for (int r = 0; r < TOPK; r++) {
            int best = -1; float bv = -2e30f;
            for (int e = 0; e < N_EXP; e++)
                if (!used[e] && s[e] > bv) { bv = s[e]; best = e; }
            used[best] = true; idx[r] = best;
        }
        float wsum = 0.f;
        for (int r = 0; r < TOPK; r++) wsum += orig[idx[r]];
        float inv = 1.f / (wsum + 1e-20f);
        for (int r = 0; r < TOPK; r++) {
            g_expt_idx[t * TOPK + r] = idx[r];
            g_expt_w[t * TOPK + r] = orig[idx[r]] * inv;
            atomicAdd(&g_counts[idx[r]], 1);
        }
    }
}

// merged offsets + scatter: one block, 1024 threads
__global__ void route_kernel() {
    if (threadIdx.x == 0) {
        int acc = 0;
        for (int e = 0; e < N_EXP; e++) {
            g_offsets[e] = acc;
            g_cursor[e] = acc;
            acc += g_counts[e];
        }
    }
    __syncthreads();
    for (int i = threadIdx.x; i < NSLOT; i += 1024) {
        int e = g_expt_idx[i];
        int pos = atomicAdd(&g_cursor[e], 1);
        g_perm_token[pos] = i >> 2;
        g_perm_w[pos] = g_expt_w[i];
        g_slot_of[i] = pos;
    }
}

// ---------------- final combine (float4) ----------------
__global__ void final_kernel(float* __restrict__ out) {
    int t = blockIdx.x;
    int s0 = g_slot_of[t * 4 + 0], s1 = g_slot_of[t * 4 + 1];
    int s2 = g_slot_of[t * 4 + 2], s3 = g_slot_of[t * 4 + 3];
    int i = threadIdx.x;
    const float4* x2v = (const float4*)(g_x2 + (size_t)t * DIM);
    const float4* zbv = (const float4*)(g_zb + (size_t)t * DIM);
    const float4* y0 = (const float4*)(g_ybuf + (size_t)s0 * DIM);
    const float4* y1 = (const float4*)(g_ybuf + (size_t)s1 * DIM);
    const float4* y2 = (const float4*)(g_ybuf + (size_t)s2 * DIM);
    const float4* y3 = (const float4*)(g_ybuf + (size_t)s3 * DIM);
    float4 a = x2v[i], b = zbv[i], c0 = y0[i], c1 = y1[i], c2 = y2[i], c3 = y3[i];
    float4 r = make_float4(a.x + b.x + c0.x + c1.x + c2.x + c3.x,
                           a.y + b.y + c0.y + c1.y + c2.y + c3.y,
                           a.z + b.z + c0.z + c1.z + c2.z + c3.z,
                           a.w + b.w + c0.w + c1.w + c2.w + c3.w);
    *(float4*)(out + (size_t)t * DIM + i * 4) = r;
}

// ---------------- launcher ----------------
extern "C" void kernel_launch(void* const* d_in, const int* in_sizes, int n_in,
                              void* d_out, int out_size) {
    const float* x       = (const float*)d_in[0];
    const float* norm_a  = (const float*)d_in[1];
    const float* wq      = (const float*)d_in[2];
    const float* wkv_a   = (const float*)d_in[3];
    const float* kvnw    = (const float*)d_in[4];
    const float* wkv_b   = (const float*)d_in[5];
    const float* wo      = (const float*)d_in[6];
    const float* norm_m  = (const float*)d_in[7];
    const float* gate_w  = (const float*)d_in[8];
    const float* gate_b  = (const float*)d_in[9];
    const float* ew1     = (const float*)d_in[10];
    const float* ew2     = (const float*)d_in[11];
    const float* ew3     = (const float*)d_in[12];
    const float* sw1     = (const float*)d_in[13];
    const float* sw2     = (const float*)d_in[14];
    const float* sw3     = (const float*)d_in[15];
    float* out = (float*)d_out;

    float *kvF, *x2, *xf, *ybuf, *zb;
    f16 *x1h, *qh, *cnh, *kvph, *khh, *Ph, *attnh, *xfh, *hbufh, *hsh;
    cudaGetSymbolAddress((void**)&kvF, g_kvF);
    cudaGetSymbolAddress((void**)&x2,  g_x2);
    cudaGetSymbolAddress((void**)&xf,  g_xf);
    cudaGetSymbolAddress((void**)&ybuf,g_ybuf);
    cudaGetSymbolAddress((void**)&zb,  g_zb);
    cudaGetSymbolAddress((void**)&x1h, g_x1h);
    cudaGetSymbolAddress((void**)&qh,  g_qh);
    cudaGetSymbolAddress((void**)&cnh, g_cnh);
    cudaGetSymbolAddress((void**)&kvph,g_kvph);
    cudaGetSymbolAddress((void**)&khh, g_khh);
    cudaGetSymbolAddress((void**)&Ph,  g_Ph);
    cudaGetSymbolAddress((void**)&attnh, g_attnh);
    cudaGetSymbolAddress((void**)&xfh, g_xfh);
    cudaGetSymbolAddress((void**)&hbufh, g_hbufh);
    cudaGetSymbolAddress((void**)&hsh, g_hsh);

    static cudaStream_t s1 = nullptr;
    static cudaEvent_t evF1, evJ1, evF2, evJ2, evRoute;
    if (!s1) {
        cudaStreamCreateWithFlags(&s1, cudaStreamNonBlocking);
        cudaEventCreateWithFlags(&evF1, cudaEventDisableTiming);
        cudaEventCreateWithFlags(&evJ1, cudaEventDisableTiming);
        cudaEventCreateWithFlags(&evF2, cudaEventDisableTiming);
        cudaEventCreateWithFlags(&evJ2, cudaEventDisableTiming);
        cudaEventCreateWithFlags(&evRoute, cudaEventDisableTiming);
    }

    // 0) zero expert counts (no deps — hoisted out of the routing chain)
    zero_counts_kernel<<<1, 32>>>();
    // 1) attention input norm -> fp16
    rmsnorm_kernel<<<TTOK, 256>>>(x, norm_a, nullptr, x1h, DIM, DIM);

    // ---- fork 1: q-proj on s1, kv chain on main ----
    cudaEventRecord(evF1, 0);
    cudaStreamWaitEvent(s1, evF1, 0);
    gemm_k<0,0,true,0,2><<<dim3(16,16,1), 256, 0, s1>>>(x1h, wq, qh, nullptr,
        TTOK, DIM, DIM, DIM, DIM, DIM, 1, 0,0,0,0,0,0, 0);
    gemm_k<0,0,false,0,2><<<dim3(5,16,1), 256>>>(x1h, wkv_a, kvF, nullptr,
        TTOK, KVA_N, DIM, DIM, KVA_N, KVA_N, 1, 0,0,0,0,0,0, 0);
    rmsnorm_kernel<<<TTOK, 256>>>(kvF, kvnw, nullptr, cnh, KV_LORA, KVA_N);
    gemm_k<0,0,true,0,2><<<dim3(24,16,1), 256>>>(cnh, wkv_b, kvph, nullptr,
        TTOK, KVB_N, KV_LORA, KV_LORA, KVB_N, KVB_N, 1, 0,0,0,0,0,0, 0);
    prep_k_kernel<<<(int)(((long long)BH*SEQ*QK_HD + 255)/256), 256>>>(kvph, kvF, khh);
    cudaEventRecord(evJ1, s1);
    cudaStreamWaitEvent(0, evJ1, 0);

    // 7) scores = q @ kh^T, triangular 128x64 tiles, f16 out into Ph
    gemm_k<0,2,true,1,2><<<dim3(72,1,BH), 256>>>(qh, khh, Ph, nullptr,
        SEQ, SEQ, QK_HD, DIM, QK_HD, SEQ, HEADS,
        (long long)SEQ*DIM, 128,
        (long long)HEADS*SEQ*QK_HD, (long long)SEQ*QK_HD,
        (long long)HEADS*SEQ*SEQ, (long long)SEQ*SEQ, 0);
    // 8) causal softmax in-place on Ph
    softmax_kernel<<<dim3(SEQ, BH), 256>>>(Ph);
    // 9) attn = P @ V
    gemm_k<0,1,true,2,2><<<dim3(2,8,BH), 256>>>(Ph, kvph + NOPE, attnh, nullptr,
        SEQ, V_HD, SEQ, SEQ, KVB_N, DIM, HEADS,
        (long long)HEADS*SEQ*SEQ, (long long)SEQ*SEQ,
        (long long)SEQ*KVB_N, (long long)(NOPE+V_HD),
        (long long)SEQ*DIM, 128, 0);
    // 10) x2 = x + attn @ wo
    gemm_k<0,0,false,0,2><<<dim3(16,16,1), 256>>>(attnh, wo, x2, x,
        TTOK, DIM, DIM, DIM, DIM, DIM, 1, 0,0,0,0,0,0, 0);
    // 11) moe input norm
    rmsnorm_kernel<<<TTOK, 256>>>(x2, norm_m, xf, xfh, DIM, DIM);

    // ---- fork 2: shared expert + routed half B on s1, routing + half A on main ----
    cudaEventRecord(evF2, 0);
    cudaStreamWaitEvent(s1, evF2, 0);
    // shared expert (s1)
    gemm_dual<0,2><<<dim3(8,16,1), 256, 0, s1>>>(xfh, sw1, sw3, hsh,
        TTOK, INTER, DIM, DIM, 0, 0);
    gemm_k<0,0,false,0,2><<<dim3(16,16,1), 256, 0, s1>>>(hsh, sw2, zb, nullptr,
        TTOK, DIM, INTER, INTER, DIM, DIM, 1, 0,0,0,0,0,0, 0);

    // routing (main)
    gate_kernel<<<TTOK, 128>>>(xf, gate_w, gate_b);
    route_kernel<<<1, 1024>>>();
    cudaEventRecord(evRoute, 0);

    // routed experts half A (experts 0-15) on main
    gemm_dual<1,2><<<dim3(8,16,16), 256>>>(xfh, ew1, ew3, hbufh,
        0, INTER, DIM, DIM, (long long)DIM*INTER, 0);
    gemm_k<2,0,false,0,2><<<dim3(16,16,16), 256>>>(hbufh, ew2, ybuf, nullptr,
        0, DIM, INTER, INTER, DIM, DIM, 1, 0,0, (long long)INTER*DIM,0, 0,0, 0);

    // routed experts half B (experts 16-31) on s1 (after shared expert + routing)
    cudaStreamWaitEvent(s1, evRoute, 0);
    gemm_dual<1,2><<<dim3(8,16,16), 256, 0, s1>>>(xfh, ew1, ew3, hbufh,
        0, INTER, DIM, DIM, (long long)DIM*INTER, 16);
    gemm_k<2,0,false,0,2><<<dim3(16,16,16), 256, 0, s1>>>(hbufh, ew2, ybuf, nullptr,
        0, DIM, INTER, INTER, DIM, DIM, 1, 0,0, (long long)INTER*DIM,0, 0,0, 16);
    cudaEventRecord(evJ2, s1);
    cudaStreamWaitEvent(0, evJ2, 0);

    // 15) final combine
    final_kernel<<<TTOK, 256>>>(out);
}

// round 15
// speedup vs baseline: 1.1097x; 1.0152x over previous
#include <cuda_runtime.h>
#include <cuda_fp16.h>
#include <math.h>
#include <stdint.h>

// ---------------- problem constants ----------------
#define TTOK   2048
#define BATCH  2
#define SEQ    1024
#define DIM    1024
#define HEADS  8
#define BH     16
#define QK_HD  128
#define V_HD   128
#define NOPE   64
#define ROPE   64
#define KV_LORA 256
#define KVA_N  320
#define KVB_N  1536
#define N_EXP  32
#define N_GROUPS 8
#define TOPK   4
#define TOPK_G 4
#define INTER  512
#define NSLOT  8192
#define EPS    1e-6f
#define ATTN_SCALE 0.08838834764831843f

typedef __half f16;

// ---------------- scratch ----------------
__device__ float g_kvF [TTOK * KVA_N];
__device__ float g_x2  [TTOK * DIM];
__device__ float g_xf  [TTOK * DIM];
__device__ float g_ybuf[NSLOT * DIM];
__device__ float g_zb  [TTOK * DIM];

__device__ f16 g_x1h [TTOK * DIM];
__device__ f16 g_qh  [TTOK * DIM];
__device__ f16 g_cnh [TTOK * KV_LORA];
__device__ f16 g_kvph[TTOK * KVB_N];
__device__ f16 g_khh [(size_t)BH * SEQ * QK_HD];
__device__ f16 g_Ph  [(size_t)BH * SEQ * SEQ];
__device__ f16 g_attnh[TTOK * DIM];
__device__ f16 g_xfh [TTOK * DIM];
__device__ f16 g_hbufh[NSLOT * INTER];
__device__ f16 g_hsh [TTOK * INTER];

__device__ int   g_counts [N_EXP];
__device__ int   g_offsets[N_EXP];
__device__ int   g_cursor [N_EXP];
__device__ int   g_expt_idx[NSLOT];
__device__ float g_expt_w [NSLOT];
__device__ int   g_perm_token[NSLOT];
__device__ float g_perm_w   [NSLOT];
__device__ int   g_slot_of  [NSLOT];

// ---------------- helpers ----------------
__device__ __forceinline__ float blockReduceSum256(float v) {
    __shared__ float red[8];
    int lane = threadIdx.x & 31, warp = threadIdx.x >> 5;
    #pragma unroll
    for (int o = 16; o > 0; o >>= 1) v += __shfl_xor_sync(0xffffffffu, v, o);
    if (lane == 0) red[warp] = v;
    __syncthreads();
    if (warp == 0) {
        v = (lane < 8) ? red[lane] : 0.f;
        #pragma unroll
        for (int o = 4; o > 0; o >>= 1) v += __shfl_xor_sync(0xffffffffu, v, o);
        if (lane == 0) red[0] = v;
    }
    __syncthreads();
    return red[0];
}

__device__ __forceinline__ float blockReduceMax256(float v) {
    __shared__ float red[8];
    int lane = threadIdx.x & 31, warp = threadIdx.x >> 5;
    #pragma unroll
    for (int o = 16; o > 0; o >>= 1) v = fmaxf(v, __shfl_xor_sync(0xffffffffu, v, o));
    if (lane == 0) red[warp] = v;
    __syncthreads();
    if (warp == 0) {
        v = (lane < 8) ? red[lane] : -1e30f;
        #pragma unroll
        for (int o = 4; o > 0; o >>= 1) v = fmaxf(v, __shfl_xor_sync(0xffffffffu, v, o));
        if (lane == 0) red[0] = v;
    }
    __syncthreads();
    return red[0];
}

__device__ __forceinline__ void mma_f16(float* c, const uint32_t* a, const uint32_t* b) {
    asm volatile(
        "mma.sync.aligned.m16n8k16.row.col.f32.f16.f16.f32 "
        "{%0,%1,%2,%3}, {%4,%5,%6,%7}, {%8,%9}, {%0,%1,%2,%3};\n"
        : "+f"(c[0]), "+f"(c[1]), "+f"(c[2]), "+f"(c[3])
        : "r"(a[0]), "r"(a[1]), "r"(a[2]), "r"(a[3]), "r"(b[0]), "r"(b[1]));
}

__device__ __forceinline__ int swA(int row) { return ((row >> 1) & 3) << 2; }
__device__ __forceinline__ int swB(int col) { return (((col >> 1) & 3) << 2) ^ ((col >> 2) & 3); }

__device__ __forceinline__ float silu_f(float a) { return a / (1.f + __expf(-a)); }

// ---------------- rmsnorm (float4 vectorized) ----------------
__global__ void rmsnorm_kernel(const float* __restrict__ x, const float* __restrict__ w,
                               float* __restrict__ o32, f16* __restrict__ o16,
                               int D, int in_stride) {
    int t = blockIdx.x;
    const float4* row = (const float4*)(x + (size_t)t * in_stride);
    const float4* wv4 = (const float4*)w;
    int nv = D >> 2;
    float ss = 0.f;
    for (int i = threadIdx.x; i < nv; i += 256) {
        float4 v = row[i];
        ss += v.x * v.x + v.y * v.y + v.z * v.z + v.w * v.w;
    }
    ss = blockReduceSum256(ss);
    __shared__ float inv;
    if (threadIdx.x == 0) inv = rsqrtf(ss / (float)D + EPS);
    __syncthreads();
    float iv = inv;
    for (int i = threadIdx.x; i < nv; i += 256) {
        float4 v = row[i];
        float4 wv = wv4[i];
        float4 r = make_float4(v.x * iv * wv.x, v.y * iv * wv.y,
                               v.z * iv * wv.z, v.w * iv * wv.w);
        if (o32) *(float4*)(o32 + (size_t)t * D + i * 4) = r;
        if (o16) {
            __half2* oh = (__half2*)(o16 + (size_t)t * D + i * 4);
            oh[0] = __floats2half2_rn(r.x, r.y);
            oh[1] = __floats2half2_rn(r.z, r.w);
        }
    }
}

// ---------------- fp16 tensor-core GEMM -----------------------------------
// CTA tile: 128 x (WN*32). MODE 0: dense; MODE 1: A gathered; MODE 2: expert
// offset + perm_w scale. BLAY: 0 = B fp32 [K][N]; 1 = B f16 [K][N]; 2 = B f16 [N][K].
// CBF: C f16. CAUSAL: 0 none; 1 triangular decode; 2 K clip at bm+128.
// zbase: expert/batch z offset.
template<int MODE, int BLAY, bool CBF, int CAUSAL, int WN>
__global__ void __launch_bounds__(256)
gemm_k(const f16* __restrict__ A, const void* __restrict__ Bv, void* __restrict__ Cv,
       const float* __restrict__ resid,
       int M, int N, int K, int lda, int ldb, int ldc, int zdiv,
       long long sA1, long long sA2, long long sB1, long long sB2,
       long long sC1, long long sC2, int zbase) {
    const int NCOLS = WN * 32;
    __shared__ uint32_t As32[2][2048];
    __shared__ uint32_t Bs32[2][WN * 512];
    __shared__ int stoks[128];

    int tid = threadIdx.x;
    int warp = tid >> 5, lane = tid & 31;
    int g = lane >> 2, tg = lane & 3;
    int wm = warp / WN, wn = warp % WN;
    int m0w = wm * (WN * 16), n0w = wn * 32;

    int bn, bm;
    if (CAUSAL == 1) {
        const int R = 128 / NCOLS;
        int ti = blockIdx.x;
        int bmt = 0;
        while (R * (bmt + 1) * (bmt + 2) / 2 <= ti) bmt++;
        int bnt = ti - R * bmt * (bmt + 1) / 2;
        bm = bmt * 128; bn = bnt * NCOLS;
    } else {
        bn = blockIdx.x * NCOLS;
        bm = blockIdx.y * 128;
    }
    int z = blockIdx.z + zbase;
    long long offA = (long long)(z / zdiv) * sA1 + (long long)(z % zdiv) * sA2;
    long long offB = (long long)(z / zdiv) * sB1 + (long long)(z % zdiv) * sB2;
    long long offC = (long long)(z / zdiv) * sC1 + (long long)(z % zdiv) * sC2;

    int cnt = M, base = 0;
    if (MODE != 0) {
        cnt = g_counts[z];
        base = g_offsets[z];
        if (bm >= cnt) return;
    }
    if (MODE == 1) {
        if (tid < 128) stoks[tid] = (bm + tid < cnt) ? g_perm_token[base + bm + tid] : 0;
        __syncthreads();
    }

    const f16* Ap = A + offA;
    const float* Bf = (BLAY == 0) ? ((const float*)Bv + offB) : nullptr;
    const f16*  Bh = (BLAY != 0) ? ((const f16*)Bv + offB) : nullptr;

    int Keff = K;
    if (CAUSAL == 2) { int kl = bm + 128; Keff = kl < K ? kl : K; }

    float cacc[WN][4][4];
    #pragma unroll
    for (int a = 0; a < WN; a++)
        #pragma unroll
        for (int b = 0; b < 4; b++)
            #pragma unroll
            for (int c = 0; c < 4; c++) cacc[a][b][c] = 0.f;

    uint4 rA[2];
    float4 rBf[WN];
    uint4 rBh[(WN + 1) / 2];

    auto stage = [&](int kk) {
        #pragma unroll
        for (int i = 0; i < 2; i++) {
            int fidx = tid + i * 256;
            int r = fidx >> 2, c8 = fidx & 3;
            uint4 v = make_uint4(0, 0, 0, 0);
            if (MODE == 0) {
                int row = bm + r;
                if (row < M) v = *(const uint4*)(Ap + (size_t)row * lda + kk + c8 * 8);
            } else if (MODE == 1) {
                if (bm + r < cnt) {
                    int tok = stoks[r];
                    v = *(const uint4*)(Ap + (size_t)tok * lda + kk + c8 * 8);
                }
            } else {
                if (bm + r < cnt)
                    v = *(const uint4*)(Ap + (size_t)(base + bm + r) * lda + kk + c8 * 8);
            }
            rA[i] = v;
        }
        if (BLAY == 0) {
            #pragma unroll
            for (int i = 0; i < WN; i++) {
                int fidx = tid + i * 256;
                int r = fidx / (NCOLS / 4), c4 = fidx % (NCOLS / 4);
                int col = bn + c4 * 4;
                float4 v = make_float4(0.f, 0.f, 0.f, 0.f);
                if (col < N) v = *(const float4*)(Bf + (size_t)(kk + r) * ldb + col);
                rBf[i] = v;
            }
        } else if (BLAY == 1) {
            #pragma unroll
            for (int i = 0; i < (WN + 1) / 2; i++) {
                int fidx = tid + i * 256;
                int r = fidx / (NCOLS / 8), c8 = fidx % (NCOLS / 8);
                if (r < 32) {
                    int col = bn + c8 * 8;
                    uint4 v = make_uint4(0, 0, 0, 0);
                    if (col < N) v = *(const uint4*)(Bh + (size_t)(kk + r) * ldb + col);
                    rBh[i] = v;
                }
            }
        } else {
            #pragma unroll
            for (int i = 0; i < (WN + 1) / 2; i++) {
                int fidx = tid + i * 256;
                int r = fidx >> 2, c8 = fidx & 3;
                if (r < NCOLS) {
                    uint4 v = make_uint4(0, 0, 0, 0);
                    if (bn + r < N) v = *(const uint4*)(Bh + (size_t)(bn + r) * ldb + kk + c8 * 8);
                    rBh[i] = v;
                }
            }
        }
    };

    auto commit = [&](int buf) {
        #pragma unroll
        for (int i = 0; i < 2; i++) {
            int fidx = tid + i * 256;
            int r = fidx >> 2, c8 = fidx & 3;
            int slotblk = (c8 * 4) ^ swA(r);
            *(uint4*)&As32[buf][r * 16 + slotblk] = rA[i];
        }
        if (BLAY == 0) {
            uint16_t* Bs16 = (uint16_t*)Bs32[buf];
            #pragma unroll
            for (int i = 0; i < WN; i++) {
                int fidx = tid + i * 256;
                int r = fidx / (NCOLS / 4), c4 = fidx % (NCOLS / 4);
                int sig = r >> 1, odd = r & 1;
                float vv[4] = {rBf[i].x, rBf[i].y, rBf[i].z, rBf[i].w};
                #pragma unroll
                for (int j = 0; j < 4; j++) {
                    int col = c4 * 4 + j;
                    f16 hv = __float2half_rn(vv[j]);
                    Bs16[col * 32 + (sig ^ swB(col)) * 2 + odd] = *(uint16_t*)&hv;
                }
            }
        } else if (BLAY == 1) {
            uint16_t* Bs16 = (uint16_t*)Bs32[buf];
            #pragma unroll
            for (int i = 0; i < (WN + 1) / 2; i++) {
                int fidx = tid + i * 256;
                int r = fidx / (NCOLS / 8), c8 = fidx % (NCOLS / 8);
                if (r < 32) {
                    int sig = r >> 1, odd = r & 1;
                    const uint16_t* src = (const uint16_t*)&rBh[i];
                    #pragma unroll
                    for (int j = 0; j < 8; j++) {
                        int col = c8 * 8 + j;
                        Bs16[col * 32 + (sig ^ swB(col)) * 2 + odd] = src[j];
                    }
                }
            }
        } else {
            #pragma unroll
            for (int i = 0; i < (WN + 1) / 2; i++) {
                int fidx = tid + i * 256;
                int r = fidx >> 2, c8 = fidx & 3;
                if (r < NCOLS) {
                    int slotblk = (c8 * 4) ^ swA(r);
                    *(uint4*)&Bs32[buf][r * 16 + slotblk] = rBh[i];
                }
            }
        }
    };

    auto compute = [&](int buf) {
        #pragma unroll
        for (int ks = 0; ks < 2; ks++) {
            int sb = ks * 8;
            uint32_t afr[WN][4], bfr[4][2];
            #pragma unroll
            for (int mt = 0; mt < WN; mt++) {
                int r0 = m0w + mt * 16 + g;
                int r1 = r0 + 8;
                afr[mt][0] = As32[buf][r0 * 16 + ((sb + tg) ^ swA(r0))];
                afr[mt][1] = As32[buf][r1 * 16 + ((sb + tg) ^ swA(r1))];
                afr[mt][2] = As32[buf][r0 * 16 + ((sb + tg + 4) ^ swA(r0))];
                afr[mt][3] = As32[buf][r1 * 16 + ((sb + tg + 4) ^ swA(r1))];
            }
            #pragma unroll
            for (int nt = 0; nt < 4; nt++) {
                int c0 = n0w + nt * 8 + g;
                int sw = (BLAY == 2) ? swA(c0) : swB(c0);
                bfr[nt][0] = Bs32[buf][c0 * 16 + ((sb + tg) ^ sw)];
                bfr[nt][1] = Bs32[buf][c0 * 16 + ((sb + tg + 4) ^ sw)];
            }
            #pragma unroll
            for (int mt = 0; mt < WN; mt++)
                #pragma unroll
                for (int nt = 0; nt < 4; nt++)
                    mma_f16(cacc[mt][nt], afr[mt], bfr[nt]);
        }
    };

    stage(0);
    commit(0);
    if (Keff > 32) stage(32);
    __syncthreads();
    int buf = 0;
    for (int kk = 0; kk < Keff; kk += 32) {
        if (kk + 32 < Keff) {
            commit(buf ^ 1);
            if (kk + 64 < Keff) stage(kk + 64);
        }
        compute(buf);
        __syncthreads();
        buf ^= 1;
    }

    float* Cf = (float*)Cv + offC;
    f16* Ch = (f16*)Cv + offC;
    #pragma unroll
    for (int mt = 0; mt < WN; mt++) {
        #pragma unroll
        for (int half_ = 0; half_ < 2; half_++) {
            int lr = bm + m0w + mt * 16 + g + half_ * 8;
            bool rowok = (MODE == 0) ? (lr < M) : (lr < cnt);
            if (!rowok) continue;
            size_t orow = (MODE == 0) ? (size_t)lr : (size_t)(base + lr);
            float scale = (MODE == 2) ? g_perm_w[base + lr] : 1.f;
            #pragma unroll
            for (int nt = 0; nt < 4; nt++) {
                int col = bn + n0w + nt * 8 + 2 * tg;
                if (col >= N) continue;
                float v0 = cacc[mt][nt][half_ * 2 + 0];
                float v1 = cacc[mt][nt][half_ * 2 + 1];
                if (MODE == 2) { v0 *= scale; v1 *= scale; }
                if (CBF) {
                    *(__half2*)(Ch + orow * ldc + col) = __floats2half2_rn(v0, v1);
                } else {
                    if (MODE == 0 && resid) {
                        float2 rv = *(const float2*)(resid + orow * ldc + col);
                        v0 += rv.x; v1 += rv.y;
                    }
                    *(float2*)(Cf + orow * ldc + col) = make_float2(v0, v1);
                }
            }
        }
    }
}

// ---------------- fused gated up-proj: C = silu(A@B1) * (A@B3), f16 out ----
template<int MODE, int WN>
__global__ void __launch_bounds__(256)
gemm_dual(const f16* __restrict__ A, const float* __restrict__ B1g,
          const float* __restrict__ B3g, f16* __restrict__ C,
          int M, int N, int K, int lda, long long strB, int zbase) {
    const int NCOLS = WN * 32;
    __shared__ uint32_t As32[2][2048];
    __shared__ uint32_t B1s32[2][WN * 512];
    __shared__ uint32_t B3s32[2][WN * 512];
    __shared__ int stoks[128];

    int tid = threadIdx.x;
    int warp = tid >> 5, lane = tid & 31;
    int g = lane >> 2, tg = lane & 3;
    int wm = warp / WN, wn = warp % WN;
    int m0w = wm * (WN * 16), n0w = wn * 32;

    int bn = blockIdx.x * NCOLS;
    int bm = blockIdx.y * 128;
    int z = blockIdx.z + zbase;

    int cnt = M, base = 0;
    if (MODE == 1) {
        cnt = g_counts[z];
        base = g_offsets[z];
        if (bm >= cnt) return;
        if (tid < 128) stoks[tid] = (bm + tid < cnt) ? g_perm_token[base + bm + tid] : 0;
        __syncthreads();
    }
    const float* B1 = B1g + (long long)z * strB;
    const float* B3 = B3g + (long long)z * strB;

    float acc1[WN][4][4], acc3[WN][4][4];
    #pragma unroll
    for (int a = 0; a < WN; a++)
        #pragma unroll
        for (int b = 0; b < 4; b++)
            #pragma unroll
            for (int c = 0; c < 4; c++) { acc1[a][b][c] = 0.f; acc3[a][b][c] = 0.f; }

    uint4 rA[2];
    float4 rB1[WN], rB3[WN];

    auto stage = [&](int kk) {
        #pragma unroll
        for (int i = 0; i < 2; i++) {
            int fidx = tid + i * 256;
            int r = fidx >> 2, c8 = fidx & 3;
            uint4 v = make_uint4(0, 0, 0, 0);
            if (MODE == 0) {
                if (bm + r < M) v = *(const uint4*)(A + (size_t)(bm + r) * lda + kk + c8 * 8);
            } else {
                if (bm + r < cnt) {
                    int tok = stoks[r];
                    v = *(const uint4*)(A + (size_t)tok * lda + kk + c8 * 8);
                }
            }
            rA[i] = v;
        }
        #pragma unroll
        for (int i = 0; i < WN; i++) {
            int fidx = tid + i * 256;
            int r = fidx / (NCOLS / 4), c4 = fidx % (NCOLS / 4);
            int col = bn + c4 * 4;
            float4 v1 = make_float4(0.f, 0.f, 0.f, 0.f);
            float4 v3 = v1;
            if (col < N) {
                v1 = *(const float4*)(B1 + (size_t)(kk + r) * N + col);
                v3 = *(const float4*)(B3 + (size_t)(kk + r) * N + col);
            }
            rB1[i] = v1; rB3[i] = v3;
        }
    };

    auto commit = [&](int buf) {
        #pragma unroll
        for (int i = 0; i < 2; i++) {
            int fidx = tid + i * 256;
            int r = fidx >> 2, c8 = fidx & 3;
            int slotblk = (c8 * 4) ^ swA(r);
            *(uint4*)&As32[buf][r * 16 + slotblk] = rA[i];
        }
        uint16_t* b1 = (uint16_t*)B1s32[buf];
        uint16_t* b3 = (uint16_t*)B3s32[buf];
        #pragma unroll
        for (int i = 0; i < WN; i++) {
            int fidx = tid + i * 256;
            int r = fidx / (NCOLS / 4), c4 = fidx % (NCOLS / 4);
            int sig = r >> 1, odd = r & 1;
            float w1[4] = {rB1[i].x, rB1[i].y, rB1[i].z, rB1[i].w};
            float w3[4] = {rB3[i].x, rB3[i].y, rB3[i].z, rB3[i].w};
            #pragma unroll
            for (int j = 0; j < 4; j++) {
                int col = c4 * 4 + j;
                int slot = (sig ^ swB(col)) * 2 + odd;
                f16 h1 = __float2half_rn(w1[j]);
                f16 h3 = __float2half_rn(w3[j]);
                b1[col * 32 + slot] = *(uint16_t*)&h1;
                b3[col * 32 + slot] = *(uint16_t*)&h3;
            }
        }
    };

    auto compute = [&](int buf) {
        #pragma unroll
        for (int ks = 0; ks < 2; ks++) {
            int sb = ks * 8;
            uint32_t afr[WN][4], b1fr[4][2], b3fr[4][2];
            #pragma unroll
            for (int mt = 0; mt < WN; mt++) {
                int r0 = m0w + mt * 16 + g;
                int r1 = r0 + 8;
                afr[mt][0] = As32[buf][r0 * 16 + ((sb + tg) ^ swA(r0))];
                afr[mt][1] = As32[buf][r1 * 16 + ((sb + tg) ^ swA(r1))];
                afr[mt][2] = As32[buf][r0 * 16 + ((sb + tg + 4) ^ swA(r0))];
                afr[mt][3] = As32[buf][r1 * 16 + ((sb + tg + 4) ^ swA(r1))];
            }
            #pragma unroll
            for (int nt = 0; nt < 4; nt++) {
                int c0 = n0w + nt * 8 + g;
                int sw = swB(c0);
                b1fr[nt][0] = B1s32[buf][c0 * 16 + ((sb + tg) ^ sw)];
                b1fr[nt][1] = B1s32[buf][c0 * 16 + ((sb + tg + 4) ^ sw)];
                b3fr[nt][0] = B3s32[buf][c0 * 16 + ((sb + tg) ^ sw)];
                b3fr[nt][1] = B3s32[buf][c0 * 16 + ((sb + tg + 4) ^ sw)];
            }
            #pragma unroll
            for (int mt = 0; mt < WN; mt++)
                #pragma unroll
                for (int nt = 0; nt < 4; nt++) {
                    mma_f16(acc1[mt][nt], afr[mt], b1fr[nt]);
                    mma_f16(acc3[mt][nt], afr[mt], b3fr[nt]);
                }
        }
    };

    stage(0);
    commit(0);
    if (K > 32) stage(32);
    __syncthreads();
    int buf = 0;
    for (int kk = 0; kk < K; kk += 32) {
        if (kk + 32 < K) {
            commit(buf ^ 1);
            if (kk + 64 < K) stage(kk + 64);
        }
        compute(buf);
        __syncthreads();
        buf ^= 1;
    }

    #pragma unroll
    for (int mt = 0; mt < WN; mt++) {
        #pragma unroll
        for (int half_ = 0; half_ < 2; half_++) {
            int lr = bm + m0w + mt * 16 + g + half_ * 8;
            bool rowok = (MODE == 0) ? (lr < M) : (lr < cnt);
            if (!rowok) continue;
            size_t orow = (MODE == 0) ? (size_t)lr : (size_t)(base + lr);
            #pragma unroll
            for (int nt = 0; nt < 4; nt++) {
                int col = bn + n0w + nt * 8 + 2 * tg;
                if (col >= N) continue;
                float a0 = acc1[mt][nt][half_ * 2 + 0];
                float a1 = acc1[mt][nt][half_ * 2 + 1];
                float b0 = acc3[mt][nt][half_ * 2 + 0];
                float b1 = acc3[mt][nt][half_ * 2 + 1];
                *(__half2*)(C + orow * N + col) =
                    __floats2half2_rn(silu_f(a0) * b0, silu_f(a1) * b1);
            }
        }
    }
}

// ---------------- pack per-head K ----------------
__global__ void prep_k_kernel(const f16* __restrict__ kvph, const float* __restrict__ kvF,
                              f16* __restrict__ kh) {
    long long i = (long long)blockIdx.x * 256 + threadIdx.x;
    if (i >= (long long)BH * SEQ * QK_HD) return;
    int d = (int)(i & 127);
    long long zs = i >> 7;
    int s = (int)(zs & (SEQ - 1));
    int zz = (int)(zs >> 10);
    int h = zz & 7, b = zz >> 3;
    size_t t = (size_t)b * SEQ + s;
    f16 val;
    if (d < NOPE) val = kvph[t * KVB_N + h * (NOPE + V_HD) + d];
    else          val = __float2half_rn(kvF[t * KVA_N + KV_LORA + (d - NOPE)]);
    kh[i] = val;
}

// ---------------- causal softmax (f16 in-place, z offset) ----------------
__global__ void softmax_kernel(f16* __restrict__ Ph, int zb) {
    int r = blockIdx.x;
    long long zoff = (long long)(blockIdx.y + zb) * SEQ * SEQ + (long long)r * SEQ;
    f16* row = Ph + zoff;
    int n = r + 1;
    int tid = threadIdx.x;
    float v[4];
    float m = -1e30f;
    #pragma unroll
    for (int j = 0; j < 4; j++) {
        int c = tid + j * 256;
        v[j] = (c < n) ? __half2float(row[c]) : -1e30f;
        m = fmaxf(m, v[j]);
    }
    m = blockReduceMax256(m);
    float e[4], l = 0.f;
    #pragma unroll
    for (int j = 0; j < 4; j++) {
        int c = tid + j * 256;
        e[j] = (c < n) ? __expf(ATTN_SCALE * (v[j] - m)) : 0.f;
        l += e[j];
    }
    l = blockReduceSum256(l);
    float inv = 1.f / l;
    #pragma unroll
    for (int j = 0; j < 4; j++) {
        int c = tid + j * 256;
        row[c] = __float2half_rn(e[j] * inv);
    }
}

// ---------------- gate / routing ----------------
__global__ void zero_counts_kernel() {
    if (threadIdx.x < N_EXP) g_counts[threadIdx.x] = 0;
}

__global__ void gate_kernel(const float* __restrict__ xf, const float* __restrict__ gw,
                            const float* __restrict__ gb) {
    int t = blockIdx.x;
    __shared__ float sscore[N_EXP];
    int tid = threadIdx.x, warp = tid >> 5, lane = tid & 31;
    for (int e = warp; e < N_EXP; e += 4) {
        float s = 0.f;
        for (int d = lane; d < DIM; d += 32) s += xf[(size_t)t * DIM + d] * gw[(size_t)e * DIM + d];
        #pragma unroll
        for (int o = 16; o > 0; o >>= 1) s += __shfl_xor_sync(0xffffffffu, s, o);
        if (lane == 0) sscore[e] = 1.f / (1.f + expf(-s));
    }
    __syncthreads();
    if (tid == 0) {
        float orig[N_EXP], s[N_EXP];
        for (int e = 0; e < N_EXP; e++) { orig[e] = sscore[e]; s[e] = orig[e] + gb[e]; }
        float gs[N_GROUPS];
        for (int gg = 0; gg < N_GROUPS; gg++) {
            float m1 = -1e30f, m2 = -1e30f;
            for (int k = 0; k < 4; k++) {
                float v = s[gg * 4 + k];
                if (v > m1) { m2 = m1; m1 = v; } else if (v > m2) m2 = v;
            }
            gs[gg] = m1 + m2;
        }
        bool gsel[N_GROUPS] = {};
        for (int r = 0; r < TOPK_G; r++) {
            int best = -1; float bv = -1e30f;
            for (int gg = 0; gg < N_GROUPS; gg++)
                if (!gsel[gg] && gs[gg] > bv) { bv = gs[gg]; best = gg; }
            gsel[best] = true;
        }
        for (int gg = 0; gg < N_GROUPS; gg++)
            if (!gsel[gg]) for (int k = 0; k < 4; k++) s[gg * 4 + k] = -1e30f;
        int idx[TOPK]; bool used[N_EXP] = {};
        for (int r = 0; r < TOPK; r++) {
            int best = -1; float bv = -2e30f;
            for (int e = 0; e < N_EXP; e++)
                if (!used[e] && s[e] > bv) { bv = s[e]; best = e; }
            used[best] = true; idx[r] = best;
        }
        float wsum = 0.f;
        for (int r = 0; r < TOPK; r++) wsum += orig[idx[r]];
        float inv = 1.f / (wsum + 1e-20f);
        for (int r = 0; r < TOPK; r++) {
            g_expt_idx[t * TOPK + r] = idx[r];
            g_expt_w[t * TOPK + r] = orig[idx[r]] * inv;
            atomicAdd(&g_counts[idx[r]], 1);
        }
    }
}

// merged offsets + scatter: one block, 1024 threads
__global__ void route_kernel() {
    if (threadIdx.x == 0) {
        int acc = 0;
        for (int e = 0; e < N_EXP; e++) {
            g_offsets[e] = acc;
            g_cursor[e] = acc;
            acc += g_counts[e];
        }
    }
    __syncthreads();
    for (int i = threadIdx.x; i < NSLOT; i += 1024) {
        int e = g_expt_idx[i];
        int pos = atomicAdd(&g_cursor[e], 1);
        g_perm_token[pos] = i >> 2;
        g_perm_w[pos] = g_expt_w[i];
        g_slot_of[i] = pos;
    }
}

// ---------------- final combine (float4) ----------------
__global__ void final_kernel(float* __restrict__ out) {
    int t = blockIdx.x;
    int s0 = g_slot_of[t * 4 + 0], s1 = g_slot_of[t * 4 + 1];
    int s2 = g_slot_of[t * 4 + 2], s3 = g_slot_of[t * 4 + 3];
    int i = threadIdx.x;
    const float4* x2v = (const float4*)(g_x2 + (size_t)t * DIM);
    const float4* zbv = (const float4*)(g_zb + (size_t)t * DIM);
    const float4* y0 = (const float4*)(g_ybuf + (size_t)s0 * DIM);
    const float4* y1 = (const float4*)(g_ybuf + (size_t)s1 * DIM);
    const float4* y2 = (const float4*)(g_ybuf + (size_t)s2 * DIM);
    const float4* y3 = (const float4*)(g_ybuf + (size_t)s3 * DIM);
    float4 a = x2v[i], b = zbv[i], c0 = y0[i], c1 = y1[i], c2 = y2[i], c3 = y3[i];
    float4 r = make_float4(a.x + b.x + c0.x + c1.x + c2.x + c3.x,
                           a.y + b.y + c0.y + c1.y + c2.y + c3.y,
                           a.z + b.z + c0.z + c1.z + c2.z + c3.z,
                           a.w + b.w + c0.w + c1.w + c2.w + c3.w);
    *(float4*)(out + (size_t)t * DIM + i * 4) = r;
}

// ---------------- launcher ----------------
extern "C" void kernel_launch(void* const* d_in, const int* in_sizes, int n_in,
                              void* d_out, int out_size) {
    const float* x       = (const float*)d_in[0];
    const float* norm_a  = (const float*)d_in[1];
    const float* wq      = (const float*)d_in[2];
    const float* wkv_a   = (const float*)d_in[3];
    const float* kvnw    = (const float*)d_in[4];
    const float* wkv_b   = (const float*)d_in[5];
    const float* wo      = (const float*)d_in[6];
    const float* norm_m  = (const float*)d_in[7];
    const float* gate_w  = (const float*)d_in[8];
    const float* gate_b  = (const float*)d_in[9];
    const float* ew1     = (const float*)d_in[10];
    const float* ew2     = (const float*)d_in[11];
    const float* ew3     = (const float*)d_in[12];
    const float* sw1     = (const float*)d_in[13];
    const float* sw2     = (const float*)d_in[14];
    const float* sw3     = (const float*)d_in[15];
    float* out = (float*)d_out;

    float *kvF, *x2, *xf, *ybuf, *zb;
    f16 *x1h, *qh, *cnh, *kvph, *khh, *Ph, *attnh, *xfh, *hbufh, *hsh;
    cudaGetSymbolAddress((void**)&kvF, g_kvF);
    cudaGetSymbolAddress((void**)&x2,  g_x2);
    cudaGetSymbolAddress((void**)&xf,  g_xf);
    cudaGetSymbolAddress((void**)&ybuf,g_ybuf);
    cudaGetSymbolAddress((void**)&zb,  g_zb);
    cudaGetSymbolAddress((void**)&x1h, g_x1h);
    cudaGetSymbolAddress((void**)&qh,  g_qh);
    cudaGetSymbolAddress((void**)&cnh, g_cnh);
    cudaGetSymbolAddress((void**)&kvph,g_kvph);
    cudaGetSymbolAddress((void**)&khh, g_khh);
    cudaGetSymbolAddress((void**)&Ph,  g_Ph);
    cudaGetSymbolAddress((void**)&attnh, g_attnh);
    cudaGetSymbolAddress((void**)&xfh, g_xfh);
    cudaGetSymbolAddress((void**)&hbufh, g_hbufh);
    cudaGetSymbolAddress((void**)&hsh, g_hsh);

    static cudaStream_t s1 = nullptr;
    static cudaEvent_t evF1, evJ1, evPrep, evAttnB, evF2, evJ2, evRoute;
    if (!s1) {
        cudaStreamCreateWithFlags(&s1, cudaStreamNonBlocking);
        cudaEventCreateWithFlags(&evF1, cudaEventDisableTiming);
        cudaEventCreateWithFlags(&evJ1, cudaEventDisableTiming);
        cudaEventCreateWithFlags(&evPrep, cudaEventDisableTiming);
        cudaEventCreateWithFlags(&evAttnB, cudaEventDisableTiming);
        cudaEventCreateWithFlags(&evF2, cudaEventDisableTiming);
        cudaEventCreateWithFlags(&evJ2, cudaEventDisableTiming);
        cudaEventCreateWithFlags(&evRoute, cudaEventDisableTiming);
    }

    // 0) zero expert counts (no deps)
    zero_counts_kernel<<<1, 32>>>();
    // 1) attention input norm -> fp16
    rmsnorm_kernel<<<TTOK, 256>>>(x, norm_a, nullptr, x1h, DIM, DIM);

    // ---- fork 1: q-proj on s1, kv chain on main ----
    cudaEventRecord(evF1, 0);
    cudaStreamWaitEvent(s1, evF1, 0);
    gemm_k<0,0,true,0,2><<<dim3(16,16,1), 256, 0, s1>>>(x1h, wq, qh, nullptr,
        TTOK, DIM, DIM, DIM, DIM, DIM, 1, 0,0,0,0,0,0, 0);
    cudaEventRecord(evJ1, s1);
    // kv_a at WN=1 (128x32 tiles -> 160 CTAs)
    gemm_k<0,0,false,0,1><<<dim3(10,16,1), 256>>>(x1h, wkv_a, kvF, nullptr,
        TTOK, KVA_N, DIM, DIM, KVA_N, KVA_N, 1, 0,0,0,0,0,0, 0);
    rmsnorm_kernel<<<TTOK, 256>>>(kvF, kvnw, nullptr, cnh, KV_LORA, KVA_N);
    gemm_k<0,0,true,0,2><<<dim3(24,16,1), 256>>>(cnh, wkv_b, kvph, nullptr,
        TTOK, KVB_N, KV_LORA, KV_LORA, KVB_N, KVB_N, 1, 0,0,0,0,0,0, 0);
    prep_k_kernel<<<(int)(((long long)BH*SEQ*QK_HD + 255)/256), 256>>>(kvph, kvF, khh);
    cudaEventRecord(evPrep, 0);
    cudaStreamWaitEvent(0, evJ1, 0);

    // ---- attention split by (b,h): half A (z 0-7) on main, half B (z 8-15) on s1 ----
    cudaStreamWaitEvent(s1, evPrep, 0);   // s1 already has qh (it produced it)
    // half B on s1
    gemm_k<0,2,true,1,2><<<dim3(72,1,8), 256, 0, s1>>>(qh, khh, Ph, nullptr,
        SEQ, SEQ, QK_HD, DIM, QK_HD, SEQ, HEADS,
        (long long)SEQ*DIM, 128,
        (long long)HEADS*SEQ*QK_HD, (long long)SEQ*QK_HD,
        (long long)HEADS*SEQ*SEQ, (long long)SEQ*SEQ, 8);
    softmax_kernel<<<dim3(SEQ, 8), 256, 0, s1>>>(Ph, 8);
    gemm_k<0,1,true,2,2><<<dim3(2,8,8), 256, 0, s1>>>(Ph, kvph + NOPE, attnh, nullptr,
        SEQ, V_HD, SEQ, SEQ, KVB_N, DIM, HEADS,
        (long long)HEADS*SEQ*SEQ, (long long)SEQ*SEQ,
        (long long)SEQ*KVB_N, (long long)(NOPE+V_HD),
        (long long)SEQ*DIM, 128, 8);
    cudaEventRecord(evAttnB, s1);
    // half A on main
    gemm_k<0,2,true,1,2><<<dim3(72,1,8), 256>>>(qh, khh, Ph, nullptr,
        SEQ, SEQ, QK_HD, DIM, QK_HD, SEQ, HEADS,
        (long long)SEQ*DIM, 128,
        (long long)HEADS*SEQ*QK_HD, (long long)SEQ*QK_HD,
        (long long)HEADS*SEQ*SEQ, (long long)SEQ*SEQ, 0);
    softmax_kernel<<<dim3(SEQ, 8), 256>>>(Ph, 0);
    gemm_k<0,1,true,2,2><<<dim3(2,8,8), 256>>>(Ph, kvph + NOPE, attnh, nullptr,
        SEQ, V_HD, SEQ, SEQ, KVB_N, DIM, HEADS,
        (long long)HEADS*SEQ*SEQ, (long long)SEQ*SEQ,
        (long long)SEQ*KVB_N, (long long)(NOPE+V_HD),
        (long long)SEQ*DIM, 128, 0);
    cudaStreamWaitEvent(0, evAttnB, 0);

    // 10) x2 = x + attn @ wo
    gemm_k<0,0,false,0,2><<<dim3(16,16,1), 256>>>(attnh, wo, x2, x,
        TTOK, DIM, DIM, DIM, DIM, DIM, 1, 0,0,0,0,0,0, 0);
    // 11) moe input norm
    rmsnorm_kernel<<<TTOK, 256>>>(x2, norm_m, xf, xfh, DIM, DIM);

    // ---- fork 2: shared expert + routed half B on s1, routing + half A on main ----
    cudaEventRecord(evF2, 0);
    cudaStreamWaitEvent(s1, evF2, 0);
    gemm_dual<0,2><<<dim3(8,16,1), 256, 0, s1>>>(xfh, sw1, sw3, hsh,
        TTOK, INTER, DIM, DIM, 0, 0);
    gemm_k<0,0,false,0,2><<<dim3(16,16,1), 256, 0, s1>>>(hsh, sw2, zb, nullptr,
        TTOK, DIM, INTER, INTER, DIM, DIM, 1, 0,0,0,0,0,0, 0);

    gate_kernel<<<TTOK, 128>>>(xf, gate_w, gate_b);
    route_kernel<<<1, 1024>>>();
    cudaEventRecord(evRoute, 0);

    gemm_dual<1,2><<<dim3(8,16,16), 256>>>(xfh, ew1, ew3, hbufh,
        0, INTER, DIM, DIM, (long long)DIM*INTER, 0);
    gemm_k<2,0,false,0,2><<<dim3(16,16,16), 256>>>(hbufh, ew2, ybuf, nullptr,
        0, DIM, INTER, INTER, DIM, DIM, 1, 0,0, (long long)INTER*DIM,0, 0,0, 0);

    cudaStreamWaitEvent(s1, evRoute, 0);
    gemm_dual<1,2><<<dim3(8,16,16), 256, 0, s1>>>(xfh, ew1, ew3, hbufh,
        0, INTER, DIM, DIM, (long long)DIM*INTER, 16);
    gemm_k<2,0,false,0,2><<<dim3(16,16,16), 256, 0, s1>>>(hbufh, ew2, ybuf, nullptr,
        0, DIM, INTER, INTER, DIM, DIM, 1, 0,0, (long long)INTER*DIM,0, 0,0, 16);
    cudaEventRecord(evJ2, s1);
    cudaStreamWaitEvent(0, evJ2, 0);

    // 15) final combine
    final_kernel<<<TTOK, 256>>>(out);
}

// round 16
// speedup vs baseline: 1.1162x; 1.0058x over previous
#include <cuda_runtime.h>
#include <cuda_fp16.h>
#include <math.h>
#include <stdint.h>

// ---------------- problem constants ----------------
#define TTOK   2048
#define BATCH  2
#define SEQ    1024
#define DIM    1024
#define HEADS  8
#define BH     16
#define QK_HD  128
#define V_HD   128
#define NOPE   64
#define ROPE   64
#define KV_LORA 256
#define KVA_N  320
#define KVB_N  1536
#define N_EXP  32
#define N_GROUPS 8
#define TOPK   4
#define TOPK_G 4
#define INTER  512
#define NSLOT  8192
#define EPS    1e-6f
#define ATTN_SCALE 0.08838834764831843f

typedef __half f16;

// ---------------- scratch ----------------
__device__ float g_kvF [TTOK * KVA_N];
__device__ float g_x2  [TTOK * DIM];
__device__ float g_xf  [TTOK * DIM];
__device__ float g_ybuf[NSLOT * DIM];
__device__ float g_zb  [TTOK * DIM];

__device__ f16 g_x1h [TTOK * DIM];
__device__ f16 g_qh  [TTOK * DIM];
__device__ f16 g_cnh [TTOK * KV_LORA];
__device__ f16 g_kvph[TTOK * KVB_N];
__device__ f16 g_khh [(size_t)BH * SEQ * QK_HD];
__device__ f16 g_Ph  [(size_t)BH * SEQ * SEQ];
__device__ f16 g_attnh[TTOK * DIM];
__device__ f16 g_xfh [TTOK * DIM];
__device__ f16 g_hbufh[NSLOT * INTER];
__device__ f16 g_hsh [TTOK * INTER];

__device__ int   g_counts [N_EXP];
__device__ int   g_offsets[N_EXP];
__device__ int   g_cursor [N_EXP];
__device__ int   g_expt_idx[NSLOT];
__device__ float g_expt_w [NSLOT];
__device__ int   g_perm_token[NSLOT];
__device__ float g_perm_w   [NSLOT];
__device__ int   g_slot_of  [NSLOT];

// ---------------- helpers ----------------
__device__ __forceinline__ float blockReduceSum256(float v) {
    __shared__ float red[8];
    int lane = threadIdx.x & 31, warp = threadIdx.x >> 5;
    #pragma unroll
    for (int o = 16; o > 0; o >>= 1) v += __shfl_xor_sync(0xffffffffu, v, o);
    if (lane == 0) red[warp] = v;
    __syncthreads();
    if (warp == 0) {
        v = (lane < 8) ? red[lane] : 0.f;
        #pragma unroll
        for (int o = 4; o > 0; o >>= 1) v += __shfl_xor_sync(0xffffffffu, v, o);
        if (lane == 0) red[0] = v;
    }
    __syncthreads();
    return red[0];
}

__device__ __forceinline__ float blockReduceMax256(float v) {
    __shared__ float red[8];
    int lane = threadIdx.x & 31, warp = threadIdx.x >> 5;
    #pragma unroll
    for (int o = 16; o > 0; o >>= 1) v = fmaxf(v, __shfl_xor_sync(0xffffffffu, v, o));
    if (lane == 0) red[warp] = v;
    __syncthreads();
    if (warp == 0) {
        v = (lane < 8) ? red[lane] : -1e30f;
        #pragma unroll
        for (int o = 4; o > 0; o >>= 1) v = fmaxf(v, __shfl_xor_sync(0xffffffffu, v, o));
        if (lane == 0) red[0] = v;
    }
    __syncthreads();
    return red[0];
}

__device__ __forceinline__ void mma_f16(float* c, const uint32_t* a, const uint32_t* b) {
    asm volatile(
        "mma.sync.aligned.m16n8k16.row.col.f32.f16.f16.f32 "
        "{%0,%1,%2,%3}, {%4,%5,%6,%7}, {%8,%9}, {%0,%1,%2,%3};\n"
        : "+f"(c[0]), "+f"(c[1]), "+f"(c[2]), "+f"(c[3])
        : "r"(a[0]), "r"(a[1]), "r"(a[2]), "r"(a[3]), "r"(b[0]), "r"(b[1]));
}

__device__ __forceinline__ int swA(int row) { return ((row >> 1) & 3) << 2; }
__device__ __forceinline__ int swB(int col) { return (((col >> 1) & 3) << 2) ^ ((col >> 2) & 3); }

__device__ __forceinline__ float silu_f(float a) { return a / (1.f + __expf(-a)); }

// ---------------- rmsnorm (float4 vectorized) ----------------
__global__ void rmsnorm_kernel(const float* __restrict__ x, const float* __restrict__ w,
                               float* __restrict__ o32, f16* __restrict__ o16,
                               int D, int in_stride) {
    int t = blockIdx.x;
    const float4* row = (const float4*)(x + (size_t)t * in_stride);
    const float4* wv4 = (const float4*)w;
    int nv = D >> 2;
    float ss = 0.f;
    for (int i = threadIdx.x; i < nv; i += 256) {
        float4 v = row[i];
        ss += v.x * v.x + v.y * v.y + v.z * v.z + v.w * v.w;
    }
    ss = blockReduceSum256(ss);
    __shared__ float inv;
    if (threadIdx.x == 0) inv = rsqrtf(ss / (float)D + EPS);
    __syncthreads();
    float iv = inv;
    for (int i = threadIdx.x; i < nv; i += 256) {
        float4 v = row[i];
        float4 wv = wv4[i];
        float4 r = make_float4(v.x * iv * wv.x, v.y * iv * wv.y,
                               v.z * iv * wv.z, v.w * iv * wv.w);
        if (o32) *(float4*)(o32 + (size_t)t * D + i * 4) = r;
        if (o16) {
            __half2* oh = (__half2*)(o16 + (size_t)t * D + i * 4);
            oh[0] = __floats2half2_rn(r.x, r.y);
            oh[1] = __floats2half2_rn(r.z, r.w);
        }
    }
}

// ---------------- fp16 tensor-core GEMM -----------------------------------
// CTA tile: 128 x (WN*32). MODE 0: dense; MODE 1: A gathered; MODE 2: expert
// offset + perm_w scale. BLAY: 0 = B fp32 [K][N]; 1 = B f16 [K][N]; 2 = B f16 [N][K].
// CBF: C f16. CAUSAL: 0 none; 1 triangular decode; 2 K clip at bm+128.
template<int MODE, int BLAY, bool CBF, int CAUSAL, int WN>
__global__ void __launch_bounds__(256)
gemm_k(const f16* __restrict__ A, const void* __restrict__ Bv, void* __restrict__ Cv,
       const float* __restrict__ resid,
       int M, int N, int K, int lda, int ldb, int ldc, int zdiv,
       long long sA1, long long sA2, long long sB1, long long sB2,
       long long sC1, long long sC2, int zbase) {
    const int NCOLS = WN * 32;
    __shared__ uint32_t As32[2][2048];
    __shared__ uint32_t Bs32[2][WN * 512];
    __shared__ int stoks[128];

    int tid = threadIdx.x;
    int warp = tid >> 5, lane = tid & 31;
    int g = lane >> 2, tg = lane & 3;
    int wm = warp / WN, wn = warp % WN;
    int m0w = wm * (WN * 16), n0w = wn * 32;

    int bn, bm;
    if (CAUSAL == 1) {
        const int R = 128 / NCOLS;
        int ti = blockIdx.x;
        int bmt = 0;
        while (R * (bmt + 1) * (bmt + 2) / 2 <= ti) bmt++;
        int bnt = ti - R * bmt * (bmt + 1) / 2;
        bm = bmt * 128; bn = bnt * NCOLS;
    } else {
        bn = blockIdx.x * NCOLS;
        bm = blockIdx.y * 128;
    }
    int z = blockIdx.z + zbase;
    long long offA = (long long)(z / zdiv) * sA1 + (long long)(z % zdiv) * sA2;
    long long offB = (long long)(z / zdiv) * sB1 + (long long)(z % zdiv) * sB2;
    long long offC = (long long)(z / zdiv) * sC1 + (long long)(z % zdiv) * sC2;

    int cnt = M, base = 0;
    if (MODE != 0) {
        cnt = g_counts[z];
        base = g_offsets[z];
        if (bm >= cnt) return;
    }
    if (MODE == 1) {
        if (tid < 128) stoks[tid] = (bm + tid < cnt) ? g_perm_token[base + bm + tid] : 0;
        __syncthreads();
    }

    const f16* Ap = A + offA;
    const float* Bf = (BLAY == 0) ? ((const float*)Bv + offB) : nullptr;
    const f16*  Bh = (BLAY != 0) ? ((const f16*)Bv + offB) : nullptr;

    int Keff = K;
    if (CAUSAL == 2) { int kl = bm + 128; Keff = kl < K ? kl : K; }

    float cacc[WN][4][4];
    #pragma unroll
    for (int a = 0; a < WN; a++)
        #pragma unroll
        for (int b = 0; b < 4; b++)
            #pragma unroll
            for (int c = 0; c < 4; c++) cacc[a][b][c] = 0.f;

    uint4 rA[2];
    float4 rBf[WN];
    uint4 rBh[(WN + 1) / 2];

    auto stage = [&](int kk) {
        #pragma unroll
        for (int i = 0; i < 2; i++) {
            int fidx = tid + i * 256;
            int r = fidx >> 2, c8 = fidx & 3;
            uint4 v = make_uint4(0, 0, 0, 0);
            if (MODE == 0) {
                int row = bm + r;
                if (row < M) v = *(const uint4*)(Ap + (size_t)row * lda + kk + c8 * 8);
            } else if (MODE == 1) {
                if (bm + r < cnt) {
                    int tok = stoks[r];
                    v = *(const uint4*)(Ap + (size_t)tok * lda + kk + c8 * 8);
                }
            } else {
                if (bm + r < cnt)
                    v = *(const uint4*)(Ap + (size_t)(base + bm + r) * lda + kk + c8 * 8);
            }
            rA[i] = v;
        }
        if (BLAY == 0) {
            #pragma unroll
            for (int i = 0; i < WN; i++) {
                int fidx = tid + i * 256;
                int r = fidx / (NCOLS / 4), c4 = fidx % (NCOLS / 4);
                int col = bn + c4 * 4;
                float4 v = make_float4(0.f, 0.f, 0.f, 0.f);
                if (col < N) v = *(const float4*)(Bf + (size_t)(kk + r) * ldb + col);
                rBf[i] = v;
            }
        } else if (BLAY == 1) {
            #pragma unroll
            for (int i = 0; i < (WN + 1) / 2; i++) {
                int fidx = tid + i * 256;
                int r = fidx / (NCOLS / 8), c8 = fidx % (NCOLS / 8);
                if (r < 32) {
                    int col = bn + c8 * 8;
                    uint4 v = make_uint4(0, 0, 0, 0);
                    if (col < N) v = *(const uint4*)(Bh + (size_t)(kk + r) * ldb + col);
                    rBh[i] = v;
                }
            }
        } else {
            #pragma unroll
            for (int i = 0; i < (WN + 1) / 2; i++) {
                int fidx = tid + i * 256;
                int r = fidx >> 2, c8 = fidx & 3;
                if (r < NCOLS) {
                    uint4 v = make_uint4(0, 0, 0, 0);
                    if (bn + r < N) v = *(const uint4*)(Bh + (size_t)(bn + r) * ldb + kk + c8 * 8);
                    rBh[i] = v;
                }
            }
        }
    };

    auto commit = [&](int buf) {
        #pragma unroll
        for (int i = 0; i < 2; i++) {
            int fidx = tid + i * 256;
            int r = fidx >> 2, c8 = fidx & 3;
            int slotblk = (c8 * 4) ^ swA(r);
            *(uint4*)&As32[buf][r * 16 + slotblk] = rA[i];
        }
        if (BLAY == 0) {
            uint16_t* Bs16 = (uint16_t*)Bs32[buf];
            #pragma unroll
            for (int i = 0; i < WN; i++) {
                int fidx = tid + i * 256;
                int r = fidx / (NCOLS / 4), c4 = fidx % (NCOLS / 4);
                int sig = r >> 1, odd = r & 1;
                float vv[4] = {rBf[i].x, rBf[i].y, rBf[i].z, rBf[i].w};
                #pragma unroll
                for (int j = 0; j < 4; j++) {
                    int col = c4 * 4 + j;
                    f16 hv = __float2half_rn(vv[j]);
                    Bs16[col * 32 + (sig ^ swB(col)) * 2 + odd] = *(uint16_t*)&hv;
                }
            }
        } else if (BLAY == 1) {
            uint16_t* Bs16 = (uint16_t*)Bs32[buf];
            #pragma unroll
            for (int i = 0; i < (WN + 1) / 2; i++) {
                int fidx = tid + i * 256;
                int r = fidx / (NCOLS / 8), c8 = fidx % (NCOLS / 8);
                if (r < 32) {
                    int sig = r >> 1, odd = r & 1;
                    const uint16_t* src = (const uint16_t*)&rBh[i];
                    #pragma unroll
                    for (int j = 0; j < 8; j++) {
                        int col = c8 * 8 + j;
                        Bs16[col * 32 + (sig ^ swB(col)) * 2 + odd] = src[j];
                    }
                }
            }
        } else {
            #pragma unroll
            for (int i = 0; i < (WN + 1) / 2; i++) {
                int fidx = tid + i * 256;
                int r = fidx >> 2, c8 = fidx & 3;
                if (r < NCOLS) {
                    int slotblk = (c8 * 4) ^ swA(r);
                    *(uint4*)&Bs32[buf][r * 16 + slotblk] = rBh[i];
                }
            }
        }
    };

    auto compute = [&](int buf) {
        #pragma unroll
        for (int ks = 0; ks < 2; ks++) {
            int sb = ks * 8;
            uint32_t afr[WN][4], bfr[4][2];
            #pragma unroll
            for (int mt = 0; mt < WN; mt++) {
                int r0 = m0w + mt * 16 + g;
                int r1 = r0 + 8;
                afr[mt][0] = As32[buf][r0 * 16 + ((sb + tg) ^ swA(r0))];
                afr[mt][1] = As32[buf][r1 * 16 + ((sb + tg) ^ swA(r1))];
                afr[mt][2] = As32[buf][r0 * 16 + ((sb + tg + 4) ^ swA(r0))];
                afr[mt][3] = As32[buf][r1 * 16 + ((sb + tg + 4) ^ swA(r1))];
            }
            #pragma unroll
            for (int nt = 0; nt < 4; nt++) {
                int c0 = n0w + nt * 8 + g;
                int sw = (BLAY == 2) ? swA(c0) : swB(c0);
                bfr[nt][0] = Bs32[buf][c0 * 16 + ((sb + tg) ^ sw)];
                bfr[nt][1] = Bs32[buf][c0 * 16 + ((sb + tg + 4) ^ sw)];
            }
            #pragma unroll
            for (int mt = 0; mt < WN; mt++)
                #pragma unroll
                for (int nt = 0; nt < 4; nt++)
                    mma_f16(cacc[mt][nt], afr[mt], bfr[nt]);
        }
    };

    stage(0);
    commit(0);
    if (Keff > 32) stage(32);
    __syncthreads();
    int buf = 0;
    for (int kk = 0; kk < Keff; kk += 32) {
        if (kk + 32 < Keff) {
            commit(buf ^ 1);
            if (kk + 64 < Keff) stage(kk + 64);
        }
        compute(buf);
        __syncthreads();
        buf ^= 1;
    }

    float* Cf = (float*)Cv + offC;
    f16* Ch = (f16*)Cv + offC;
    #pragma unroll
    for (int mt = 0; mt < WN; mt++) {
        #pragma unroll
        for (int half_ = 0; half_ < 2; half_++) {
            int lr = bm + m0w + mt * 16 + g + half_ * 8;
            bool rowok = (MODE == 0) ? (lr < M) : (lr < cnt);
            if (!rowok) continue;
            size_t orow = (MODE == 0) ? (size_t)lr : (size_t)(base + lr);
            float scale = (MODE == 2) ? g_perm_w[base + lr] : 1.f;
            #pragma unroll
            for (int nt = 0; nt < 4; nt++) {
                int col = bn + n0w + nt * 8 + 2 * tg;
                if (col >= N) continue;
                float v0 = cacc[mt][nt][half_ * 2 + 0];
                float v1 = cacc[mt][nt][half_ * 2 + 1];
                if (MODE == 2) { v0 *= scale; v1 *= scale; }
                if (CBF) {
                    *(__half2*)(Ch + orow * ldc + col) = __floats2half2_rn(v0, v1);
                } else {
                    if (MODE == 0 && resid) {
                        float2 rv = *(const float2*)(resid + orow * ldc + col);
                        v0 += rv.x; v1 += rv.y;
                    }
                    *(float2*)(Cf + orow * ldc + col) = make_float2(v0, v1);
                }
            }
        }
    }
}

// ---------------- fused gated up-proj: C = silu(A@B1) * (A@B3), f16 out ----
template<int MODE, int WN>
__global__ void __launch_bounds__(256)
gemm_dual(const f16* __restrict__ A, const float* __restrict__ B1g,
          const float* __restrict__ B3g, f16* __restrict__ C,
          int M, int N, int K, int lda, long long strB, int zbase) {
    const int NCOLS = WN * 32;
    __shared__ uint32_t As32[2][2048];
    __shared__ uint32_t B1s32[2][WN * 512];
    __shared__ uint32_t B3s32[2][WN * 512];
    __shared__ int stoks[128];

    int tid = threadIdx.x;
    int warp = tid >> 5, lane = tid & 31;
    int g = lane >> 2, tg = lane & 3;
    int wm = warp / WN, wn = warp % WN;
    int m0w = wm * (WN * 16), n0w = wn * 32;

    int bn = blockIdx.x * NCOLS;
    int bm = blockIdx.y * 128;
    int z = blockIdx.z + zbase;

    int cnt = M, base = 0;
    if (MODE == 1) {
        cnt = g_counts[z];
        base = g_offsets[z];
        if (bm >= cnt) return;
        if (tid < 128) stoks[tid] = (bm + tid < cnt) ? g_perm_token[base + bm + tid] : 0;
        __syncthreads();
    }
    const float* B1 = B1g + (long long)z * strB;
    const float* B3 = B3g + (long long)z * strB;

    float acc1[WN][4][4], acc3[WN][4][4];
    #pragma unroll
    for (int a = 0; a < WN; a++)
        #pragma unroll
        for (int b = 0; b < 4; b++)
            #pragma unroll
            for (int c = 0; c < 4; c++) { acc1[a][b][c] = 0.f; acc3[a][b][c] = 0.f; }

    uint4 rA[2];
    float4 rB1[WN], rB3[WN];

    auto stage = [&](int kk) {
        #pragma unroll
        for (int i = 0; i < 2; i++) {
            int fidx = tid + i * 256;
            int r = fidx >> 2, c8 = fidx & 3;
            uint4 v = make_uint4(0, 0, 0, 0);
            if (MODE == 0) {
                if (bm + r < M) v = *(const uint4*)(A + (size_t)(bm + r) * lda + kk + c8 * 8);
            } else {
                if (bm + r < cnt) {
                    int tok = stoks[r];
                    v = *(const uint4*)(A + (size_t)tok * lda + kk + c8 * 8);
                }
            }
            rA[i] = v;
        }
        #pragma unroll
        for (int i = 0; i < WN; i++) {
            int fidx = tid + i * 256;
            int r = fidx / (NCOLS / 4), c4 = fidx % (NCOLS / 4);
            int col = bn + c4 * 4;
            float4 v1 = make_float4(0.f, 0.f, 0.f, 0.f);
            float4 v3 = v1;
            if (col < N) {
                v1 = *(const float4*)(B1 + (size_t)(kk + r) * N + col);
                v3 = *(const float4*)(B3 + (size_t)(kk + r) * N + col);
            }
            rB1[i] = v1; rB3[i] = v3;
        }
    };

    auto commit = [&](int buf) {
        #pragma unroll
        for (int i = 0; i < 2; i++) {
            int fidx = tid + i * 256;
            int r = fidx >> 2, c8 = fidx & 3;
            int slotblk = (c8 * 4) ^ swA(r);
            *(uint4*)&As32[buf][r * 16 + slotblk] = rA[i];
        }
        uint16_t* b1 = (uint16_t*)B1s32[buf];
        uint16_t* b3 = (uint16_t*)B3s32[buf];
        #pragma unroll
        for (int i = 0; i < WN; i++) {
            int fidx = tid + i * 256;
            int r = fidx / (NCOLS / 4), c4 = fidx % (NCOLS / 4);
            int sig = r >> 1, odd = r & 1;
            float w1[4] = {rB1[i].x, rB1[i].y, rB1[i].z, rB1[i].w};
            float w3[4] = {rB3[i].x, rB3[i].y, rB3[i].z, rB3[i].w};
            #pragma unroll
            for (int j = 0; j < 4; j++) {
                int col = c4 * 4 + j;
                int slot = (sig ^ swB(col)) * 2 + odd;
                f16 h1 = __float2half_rn(w1[j]);
                f16 h3 = __float2half_rn(w3[j]);
                b1[col * 32 + slot] = *(uint16_t*)&h1;
                b3[col * 32 + slot] = *(uint16_t*)&h3;
            }
        }
    };

    auto compute = [&](int buf) {
        #pragma unroll
        for (int ks = 0; ks < 2; ks++) {
            int sb = ks * 8;
            uint32_t afr[WN][4], b1fr[4][2], b3fr[4][2];
            #pragma unroll
            for (int mt = 0; mt < WN; mt++) {
                int r0 = m0w + mt * 16 + g;
                int r1 = r0 + 8;
                afr[mt][0] = As32[buf][r0 * 16 + ((sb + tg) ^ swA(r0))];
                afr[mt][1] = As32[buf][r1 * 16 + ((sb + tg) ^ swA(r1))];
                afr[mt][2] = As32[buf][r0 * 16 + ((sb + tg + 4) ^ swA(r0))];
                afr[mt][3] = As32[buf][r1 * 16 + ((sb + tg + 4) ^ swA(r1))];
            }
            #pragma unroll
            for (int nt = 0; nt < 4; nt++) {
                int c0 = n0w + nt * 8 + g;
                int sw = swB(c0);
                b1fr[nt][0] = B1s32[buf][c0 * 16 + ((sb + tg) ^ sw)];
                b1fr[nt][1] = B1s32[buf][c0 * 16 + ((sb + tg + 4) ^ sw)];
                b3fr[nt][0] = B3s32[buf][c0 * 16 + ((sb + tg) ^ sw)];
                b3fr[nt][1] = B3s32[buf][c0 * 16 + ((sb + tg + 4) ^ sw)];
            }
            #pragma unroll
            for (int mt = 0; mt < WN; mt++)
                #pragma unroll
                for (int nt = 0; nt < 4; nt++) {
                    mma_f16(acc1[mt][nt], afr[mt], b1fr[nt]);
                    mma_f16(acc3[mt][nt], afr[mt], b3fr[nt]);
                }
        }
    };

    stage(0);
    commit(0);
    if (K > 32) stage(32);
    __syncthreads();
    int buf = 0;
    for (int kk = 0; kk < K; kk += 32) {
        if (kk + 32 < K) {
            commit(buf ^ 1);
            if (kk + 64 < K) stage(kk + 64);
        }
        compute(buf);
        __syncthreads();
        buf ^= 1;
    }

    #pragma unroll
    for (int mt = 0; mt < WN; mt++) {
        #pragma unroll
        for (int half_ = 0; half_ < 2; half_++) {
            int lr = bm + m0w + mt * 16 + g + half_ * 8;
            bool rowok = (MODE == 0) ? (lr < M) : (lr < cnt);
            if (!rowok) continue;
            size_t orow = (MODE == 0) ? (size_t)lr : (size_t)(base + lr);
            #pragma unroll
            for (int nt = 0; nt < 4; nt++) {
                int col = bn + n0w + nt * 8 + 2 * tg;
                if (col >= N) continue;
                float a0 = acc1[mt][nt][half_ * 2 + 0];
                float a1 = acc1[mt][nt][half_ * 2 + 1];
                float b0 = acc3[mt][nt][half_ * 2 + 0];
                float b1 = acc3[mt][nt][half_ * 2 + 1];
                *(__half2*)(C + orow * N + col) =
                    __floats2half2_rn(silu_f(a0) * b0, silu_f(a1) * b1);
            }
        }
    }
}

// ---------------- pack per-head K ----------------
__global__ void prep_k_kernel(const f16* __restrict__ kvph, const float* __restrict__ kvF,
                              f16* __restrict__ kh) {
    long long i = (long long)blockIdx.x * 256 + threadIdx.x;
    if (i >= (long long)BH * SEQ * QK_HD) return;
    int d = (int)(i & 127);
    long long zs = i >> 7;
    int s = (int)(zs & (SEQ - 1));
    int zz = (int)(zs >> 10);
    int h = zz & 7, b = zz >> 3;
    size_t t = (size_t)b * SEQ + s;
    f16 val;
    if (d < NOPE) val = kvph[t * KVB_N + h * (NOPE + V_HD) + d];
    else          val = __float2half_rn(kvF[t * KVA_N + KV_LORA + (d - NOPE)]);
    kh[i] = val;
}

// ---------------- causal softmax (f16 in-place, z offset) ----------------
__global__ void softmax_kernel(f16* __restrict__ Ph, int zb) {
    int r = blockIdx.x;
    long long zoff = (long long)(blockIdx.y + zb) * SEQ * SEQ + (long long)r * SEQ;
    f16* row = Ph + zoff;
    int n = r + 1;
    int tid = threadIdx.x;
    float v[4];
    float m = -1e30f;
    #pragma unroll
    for (int j = 0; j < 4; j++) {
        int c = tid + j * 256;
        v[j] = (c < n) ? __half2float(row[c]) : -1e30f;
        m = fmaxf(m, v[j]);
    }
    m = blockReduceMax256(m);
    float e[4], l = 0.f;
    #pragma unroll
    for (int j = 0; j < 4; j++) {
        int c = tid + j * 256;
        e[j] = (c < n) ? __expf(ATTN_SCALE * (v[j] - m)) : 0.f;
        l += e[j];
    }
    l = blockReduceSum256(l);
    float inv = 1.f / l;
    #pragma unroll
    for (int j = 0; j < 4; j++) {
        int c = tid + j * 256;
        row[c] = __float2half_rn(e[j] * inv);
    }
}

// ---------------- gate / routing ----------------
__global__ void zero_counts_kernel() {
    if (threadIdx.x < N_EXP) g_counts[threadIdx.x] = 0;
}

__global__ void gate_kernel(const float* __restrict__ xf, const float* __restrict__ gw,
                            const float* __restrict__ gb) {
    int t = blockIdx.x;
    __shared__ float sscore[N_EXP];
    int tid = threadIdx.x, warp = tid >> 5, lane = tid & 31;
    for (int e = warp; e < N_EXP; e += 4) {
        float s = 0.f;
        for (int d = lane; d < DIM; d += 32) s += xf[(size_t)t * DIM + d] * gw[(size_t)e * DIM + d];
        #pragma unroll
        for (int o = 16; o > 0; o >>= 1) s += __shfl_xor_sync(0xffffffffu, s, o);
        if (lane == 0) sscore[e] = 1.f / (1.f + expf(-s));
    }
    __syncthreads();
    if (tid == 0) {
        float orig[N_EXP], s[N_EXP];
        for (int e = 0; e < N_EXP; e++) { orig[e] = sscore[e]; s[e] = orig[e] + gb[e]; }
        float gs[N_GROUPS];
        for (int gg = 0; gg < N_GROUPS; gg++) {
            float m1 = -1e30f, m2 = -1e30f;
            for (int k = 0; k < 4; k++) {
                float v = s[gg * 4 + k];
                if (v > m1) { m2 = m1; m1 = v; } else if (v > m2) m2 = v;
            }
            gs[gg] = m1 + m2;
        }
        bool gsel[N_GROUPS] = {};
        for (int r = 0; r < TOPK_G; r++) {
            int best = -1; float bv = -1e30f;
            for (int gg = 0; gg < N_GROUPS; gg++)
                if (!gsel[gg] && gs[gg] > bv) { bv = gs[gg]; best = gg; }
            gsel[best] = true;
        }
        for (int gg = 0; gg < N_GROUPS; gg++)
            if (!gsel[gg]) for (int k = 0; k < 4; k++) s[gg * 4 + k] = -1e30f;
        int idx[TOPK]; bool used[N_EXP] = {};
        for (int r = 0; r < TOPK; r++) {
            int best = -1; float bv = -2e30f;
            for (int e = 0; e < N_EXP; e++)
                if (!used[e] && s[e] > bv) { bv = s[e]; best = e; }
            used[best] = true; idx[r] = best;
        }
        float wsum = 0.f;
        for (int r = 0; r < TOPK; r++) wsum += orig[idx[r]];
        float inv = 1.f / (wsum + 1e-20f);
        for (int r = 0; r < TOPK; r++) {
            g_expt_idx[t * TOPK + r] = idx[r];
            g_expt_w[t * TOPK + r] = orig[idx[r]] * inv;
            atomicAdd(&g_counts[idx[r]], 1);
        }
    }
}

// merged offsets + scatter: one block, 1024 threads
__global__ void route_kernel() {
    if (threadIdx.x == 0) {
        int acc = 0;
        for (int e = 0; e < N_EXP; e++) {
            g_offsets[e] = acc;
            g_cursor[e] = acc;
            acc += g_counts[e];
        }
    }
    __syncthreads();
    for (int i = threadIdx.x; i < NSLOT; i += 1024) {
        int e = g_expt_idx[i];
        int pos = atomicAdd(&g_cursor[e], 1);
        g_perm_token[pos] = i >> 2;
        g_perm_w[pos] = g_expt_w[i];
        g_slot_of[i] = pos;
    }
}

// ---------------- final combine (float4) ----------------
__global__ void final_kernel(float* __restrict__ out) {
    int t = blockIdx.x;
    int s0 = g_slot_of[t * 4 + 0], s1 = g_slot_of[t * 4 + 1];
    int s2 = g_slot_of[t * 4 + 2], s3 = g_slot_of[t * 4 + 3];
    int i = threadIdx.x;
    const float4* x2v = (const float4*)(g_x2 + (size_t)t * DIM);
    const float4* zbv = (const float4*)(g_zb + (size_t)t * DIM);
    const float4* y0 = (const float4*)(g_ybuf + (size_t)s0 * DIM);
    const float4* y1 = (const float4*)(g_ybuf + (size_t)s1 * DIM);
    const float4* y2 = (const float4*)(g_ybuf + (size_t)s2 * DIM);
    const float4* y3 = (const float4*)(g_ybuf + (size_t)s3 * DIM);
    float4 a = x2v[i], b = zbv[i], c0 = y0[i], c1 = y1[i], c2 = y2[i], c3 = y3[i];
    float4 r = make_float4(a.x + b.x + c0.x + c1.x + c2.x + c3.x,
                           a.y + b.y + c0.y + c1.y + c2.y + c3.y,
                           a.z + b.z + c0.z + c1.z + c2.z + c3.z,
                           a.w + b.w + c0.w + c1.w + c2.w + c3.w);
    *(float4*)(out + (size_t)t * DIM + i * 4) = r;
}

// ---------------- launcher ----------------
extern "C" void kernel_launch(void* const* d_in, const int* in_sizes, int n_in,
                              void* d_out, int out_size) {
    const float* x       = (const float*)d_in[0];
    const float* norm_a  = (const float*)d_in[1];
    const float* wq      = (const float*)d_in[2];
    const float* wkv_a   = (const float*)d_in[3];
    const float* kvnw    = (const float*)d_in[4];
    const float* wkv_b   = (const float*)d_in[5];
    const float* wo      = (const float*)d_in[6];
    const float* norm_m  = (const float*)d_in[7];
    const float* gate_w  = (const float*)d_in[8];
    const float* gate_b  = (const float*)d_in[9];
    const float* ew1     = (const float*)d_in[10];
    const float* ew2     = (const float*)d_in[11];
    const float* ew3     = (const float*)d_in[12];
    const float* sw1     = (const float*)d_in[13];
    const float* sw2     = (const float*)d_in[14];
    const float* sw3     = (const float*)d_in[15];
    float* out = (float*)d_out;

    float *kvF, *x2, *xf, *ybuf, *zb;
    f16 *x1h, *qh, *cnh, *kvph, *khh, *Ph, *attnh, *xfh, *hbufh, *hsh;
    cudaGetSymbolAddress((void**)&kvF, g_kvF);
    cudaGetSymbolAddress((void**)&x2,  g_x2);
    cudaGetSymbolAddress((void**)&xf,  g_xf);
    cudaGetSymbolAddress((void**)&ybuf,g_ybuf);
    cudaGetSymbolAddress((void**)&zb,  g_zb);
    cudaGetSymbolAddress((void**)&x1h, g_x1h);
    cudaGetSymbolAddress((void**)&qh,  g_qh);
    cudaGetSymbolAddress((void**)&cnh, g_cnh);
    cudaGetSymbolAddress((void**)&kvph,g_kvph);
    cudaGetSymbolAddress((void**)&khh, g_khh);
    cudaGetSymbolAddress((void**)&Ph,  g_Ph);
    cudaGetSymbolAddress((void**)&attnh, g_attnh);
    cudaGetSymbolAddress((void**)&xfh, g_xfh);
    cudaGetSymbolAddress((void**)&hbufh, g_hbufh);
    cudaGetSymbolAddress((void**)&hsh, g_hsh);

    static cudaStream_t s1 = nullptr;
    static cudaEvent_t evF1, evJ1, evPrep, evA, evB, evF2, evJ2, evRoute;
    if (!s1) {
        cudaStreamCreateWithFlags(&s1, cudaStreamNonBlocking);
        cudaEventCreateWithFlags(&evF1, cudaEventDisableTiming);
        cudaEventCreateWithFlags(&evJ1, cudaEventDisableTiming);
        cudaEventCreateWithFlags(&evPrep, cudaEventDisableTiming);
        cudaEventCreateWithFlags(&evA, cudaEventDisableTiming);
        cudaEventCreateWithFlags(&evB, cudaEventDisableTiming);
        cudaEventCreateWithFlags(&evF2, cudaEventDisableTiming);
        cudaEventCreateWithFlags(&evJ2, cudaEventDisableTiming);
        cudaEventCreateWithFlags(&evRoute, cudaEventDisableTiming);
    }

    const int HALF = TTOK / 2;   // 1024 rows per batch

    // 0) zero expert counts (no deps)
    zero_counts_kernel<<<1, 32>>>();
    // 1) attention input norm -> fp16
    rmsnorm_kernel<<<TTOK, 256>>>(x, norm_a, nullptr, x1h, DIM, DIM);

    // ---- fork 1: q-proj on s1, kv chain on main ----
    cudaEventRecord(evF1, 0);
    cudaStreamWaitEvent(s1, evF1, 0);
    gemm_k<0,0,true,0,2><<<dim3(16,16,1), 256, 0, s1>>>(x1h, wq, qh, nullptr,
        TTOK, DIM, DIM, DIM, DIM, DIM, 1, 0,0,0,0,0,0, 0);
    cudaEventRecord(evJ1, s1);
    gemm_k<0,0,false,0,1><<<dim3(10,16,1), 256>>>(x1h, wkv_a, kvF, nullptr,
        TTOK, KVA_N, DIM, DIM, KVA_N, KVA_N, 1, 0,0,0,0,0,0, 0);
    rmsnorm_kernel<<<TTOK, 256>>>(kvF, kvnw, nullptr, cnh, KV_LORA, KVA_N);
    gemm_k<0,0,true,0,2><<<dim3(24,16,1), 256>>>(cnh, wkv_b, kvph, nullptr,
        TTOK, KVB_N, KV_LORA, KV_LORA, KVB_N, KVB_N, 1, 0,0,0,0,0,0, 0);
    prep_k_kernel<<<(int)(((long long)BH*SEQ*QK_HD + 255)/256), 256>>>(kvph, kvF, khh);
    cudaEventRecord(evPrep, 0);
    cudaStreamWaitEvent(0, evJ1, 0);

    // ---- attention + epilogue pipelined by batch ----
    cudaStreamWaitEvent(s1, evPrep, 0);
    // batch 1 (z 8-15) on s1: attention -> o-proj rows [1024,2048) -> norm
    gemm_k<0,2,true,1,2><<<dim3(72,1,8), 256, 0, s1>>>(qh, khh, Ph, nullptr,
        SEQ, SEQ, QK_HD, DIM, QK_HD, SEQ, HEADS,
        (long long)SEQ*DIM, 128,
        (long long)HEADS*SEQ*QK_HD, (long long)SEQ*QK_HD,
        (long long)HEADS*SEQ*SEQ, (long long)SEQ*SEQ, 8);
    softmax_kernel<<<dim3(SEQ, 8), 256, 0, s1>>>(Ph, 8);
    gemm_k<0,1,true,2,2><<<dim3(2,8,8), 256, 0, s1>>>(Ph, kvph + NOPE, attnh, nullptr,
        SEQ, V_HD, SEQ, SEQ, KVB_N, DIM, HEADS,
        (long long)HEADS*SEQ*SEQ, (long long)SEQ*SEQ,
        (long long)SEQ*KVB_N, (long long)(NOPE+V_HD),
        (long long)SEQ*DIM, 128, 8);
    gemm_k<0,0,false,0,2><<<dim3(16,8,1), 256, 0, s1>>>(
        attnh + (size_t)HALF * DIM, wo, x2 + (size_t)HALF * DIM, x + (size_t)HALF * DIM,
        HALF, DIM, DIM, DIM, DIM, DIM, 1, 0,0,0,0,0,0, 0);
    rmsnorm_kernel<<<HALF, 256, 0, s1>>>(x2 + (size_t)HALF * DIM, norm_m,
        xf + (size_t)HALF * DIM, xfh + (size_t)HALF * DIM, DIM, DIM);
    cudaEventRecord(evB, s1);
    // batch 0 (z 0-7) on main: attention -> o-proj rows [0,1024) -> norm
    gemm_k<0,2,true,1,2><<<dim3(72,1,8), 256>>>(qh, khh, Ph, nullptr,
        SEQ, SEQ, QK_HD, DIM, QK_HD, SEQ, HEADS,
        (long long)SEQ*DIM, 128,
        (long long)HEADS*SEQ*QK_HD, (long long)SEQ*QK_HD,
        (long long)HEADS*SEQ*SEQ, (long long)SEQ*SEQ, 0);
    softmax_kernel<<<dim3(SEQ, 8), 256>>>(Ph, 0);
    gemm_k<0,1,true,2,2><<<dim3(2,8,8), 256>>>(Ph, kvph + NOPE, attnh, nullptr,
        SEQ, V_HD, SEQ, SEQ, KVB_N, DIM, HEADS,
        (long long)HEADS*SEQ*SEQ, (long long)SEQ*SEQ,
        (long long)SEQ*KVB_N, (long long)(NOPE+V_HD),
        (long long)SEQ*DIM, 128, 0);
    gemm_k<0,0,false,0,2><<<dim3(16,8,1), 256>>>(attnh, wo, x2, x,
        HALF, DIM, DIM, DIM, DIM, DIM, 1, 0,0,0,0,0,0, 0);
    rmsnorm_kernel<<<HALF, 256>>>(x2, norm_m, xf, xfh, DIM, DIM);
    cudaEventRecord(evA, 0);

    // ---- fork 2: shared expert + routed half B on s1, routing + half A on main ----
    // s1 needs full xfh for shared expert: wait for main's half.
    cudaStreamWaitEvent(s1, evA, 0);
    gemm_dual<0,2><<<dim3(8,16,1), 256, 0, s1>>>(xfh, sw1, sw3, hsh,
        TTOK, INTER, DIM, DIM, 0, 0);
    gemm_k<0,0,false,0,2><<<dim3(16,16,1), 256, 0, s1>>>(hsh, sw2, zb, nullptr,
        TTOK, DIM, INTER, INTER, DIM, DIM, 1, 0,0,0,0,0,0, 0);
    // main needs full xf for gate: wait for s1's half.
    cudaStreamWaitEvent(0, evB, 0);
    gate_kernel<<<TTOK, 128>>>(xf, gate_w, gate_b);
    route_kernel<<<1, 1024>>>();
    cudaEventRecord(evRoute, 0);

    gemm_dual<1,2><<<dim3(8,16,16), 256>>>(xfh, ew1, ew3, hbufh,
        0, INTER, DIM, DIM, (long long)DIM*INTER, 0);
    gemm_k<2,0,false,0,2><<<dim3(16,16,16), 256>>>(hbufh, ew2, ybuf, nullptr,
        0, DIM, INTER, INTER, DIM, DIM, 1, 0,0, (long long)INTER*DIM,0, 0,0, 0);

    cudaStreamWaitEvent(s1, evRoute, 0);
    gemm_dual<1,2><<<dim3(8,16,16), 256, 0, s1>>>(xfh, ew1, ew3, hbufh,
        0, INTER, DIM, DIM, (long long)DIM*INTER, 16);
    gemm_k<2,0,false,0,2><<<dim3(16,16,16), 256, 0, s1>>>(hbufh, ew2, ybuf, nullptr,
        0, DIM, INTER, INTER, DIM, DIM, 1, 0,0, (long long)INTER*DIM,0, 0,0, 16);
    cudaEventRecord(evJ2, s1);
    cudaStreamWaitEvent(0, evJ2, 0);

    // 15) final combine
    final_kernel<<<TTOK, 256>>>(out);
}